// round 9
// baseline (speedup 1.0000x reference)
#include <cuda_runtime.h>
#include <cstdint>
#include <math.h>

#define Bn   2
#define Ln   1024
#define Dn   1024
#define Hn   16
#define HDn  64
#define HIDn 4096
#define Mn   (Bn*Ln)        /* 2048 rows */
#define EPSc 1e-6f
#define SCALEc 0.125f       /* 64^-0.5 */

// ---------------- scratch (device globals; no runtime allocation) ----------
__device__ float g_hr[Mn*Dn],  g_hi[Mn*Dn],  g_hs[Mn*Dn];
__device__ float g_qr[Mn*Dn],  g_qi[Mn*Dn];
__device__ float g_kr[Mn*Dn],  g_ki[Mn*Dn];
__device__ float g_vr[Mn*Dn],  g_vi[Mn*Dn];
__device__ float g_s [Bn*Hn*Ln*Ln];          /* 128 MB scores/attn */
__device__ float g_aor[Mn*Dn], g_aoi[Mn*Dn], g_aos[Mn*Dn];
__device__ float g_ar[Mn*Dn],  g_ai[Mn*Dn];
__device__ float g_fr[Mn*HIDn], g_fi[Mn*HIDn], g_fs[Mn*HIDn];
// rounded weight copies + sums
__device__ float g_wq_r[Dn*Dn], g_wq_i[Dn*Dn], g_wq_s[Dn*Dn];
__device__ float g_wk_r[Dn*Dn], g_wk_i[Dn*Dn], g_wk_s[Dn*Dn];
__device__ float g_wv_r[Dn*Dn], g_wv_i[Dn*Dn], g_wv_s[Dn*Dn];
__device__ float g_wo_r[Dn*Dn], g_wo_i[Dn*Dn], g_wo_s[Dn*Dn];
__device__ float g_w1_r[HIDn*Dn], g_w1_i[HIDn*Dn], g_w1_s[HIDn*Dn];
__device__ float g_w2_r[Dn*HIDn], g_w2_i[Dn*HIDn], g_w2_s[Dn*HIDn];

// ================= helpers (baseline PTX only) ==============================
__device__ __forceinline__ uint32_t smem_u32(const void* p) {
    uint32_t a;
    asm("{ .reg .u64 t; cvta.to.shared.u64 t, %1; cvt.u32.u64 %0, t; }" : "=r"(a) : "l"(p));
    return a;
}
#define CP16(dst_u32, src_ptr) \
    asm volatile("cp.async.cg.shared.global [%0], [%1], 16;" :: "r"(dst_u32), "l"(src_ptr) : "memory")
#define CP_COMMIT() asm volatile("cp.async.commit_group;" ::: "memory")
#define CP_WAIT1()  asm volatile("cp.async.wait_group 1;" ::: "memory")
#define CP_WAIT0()  asm volatile("cp.async.wait_group 0;" ::: "memory")

__device__ __forceinline__ uint32_t f2tf32(float x) {
    uint32_t r;
    asm("cvt.rna.tf32.f32 %0, %1;" : "=r"(r) : "f"(x));
    return r;
}
__device__ __forceinline__ float rnaf(float x) { return __uint_as_float(f2tf32(x)); }

#define MMA_TF32(d, a, b) \
    asm volatile("mma.sync.aligned.m16n8k8.row.col.f32.tf32.tf32.f32 " \
        "{%0,%1,%2,%3}, {%4,%5,%6,%7}, {%8,%9}, {%0,%1,%2,%3};" \
        : "+f"((d)[0]), "+f"((d)[1]), "+f"((d)[2]), "+f"((d)[3]) \
        : "r"((a)[0]), "r"((a)[1]), "r"((a)[2]), "r"((a)[3]), \
          "r"((b)[0]), "r"((b)[1]))

#define LDSM4(r, addr) \
    asm volatile("ldmatrix.sync.aligned.m8n8.x4.shared.b16 {%0,%1,%2,%3}, [%4];" \
        : "=r"((r)[0]), "=r"((r)[1]), "=r"((r)[2]), "=r"((r)[3]) : "r"(addr))

// ================= weight prep: rounded copies + Gauss sums =================
__global__ void wprep_kernel(const float4* __restrict__ wr, const float4* __restrict__ wi,
                             float4* __restrict__ owr, float4* __restrict__ owi,
                             float4* __restrict__ ows, int n4)
{
    int i = blockIdx.x * 256 + threadIdx.x;
    if (i >= n4) return;
    float4 r = wr[i], m = wi[i], orr, oii, oss;
    orr.x = rnaf(r.x); orr.y = rnaf(r.y); orr.z = rnaf(r.z); orr.w = rnaf(r.w);
    oii.x = rnaf(m.x); oii.y = rnaf(m.y); oii.z = rnaf(m.z); oii.w = rnaf(m.w);
    oss.x = rnaf(orr.x + oii.x); oss.y = rnaf(orr.y + oii.y);
    oss.z = rnaf(orr.z + oii.z); oss.w = rnaf(orr.w + oii.w);
    owr[i] = orr; owi[i] = oii; ows[i] = oss;
}

// ================= Gauss complex GEMM, cp.async + ldmatrix ==================
// C = A @ B^T. A sets (Ar,Ai,As):[M,K], B sets:[N,K] row-major, tf32-rounded.
// Block 128x64, BK=32, 8 warps (4m x 2n), warp tile 32x32.
#define BMg 128
#define BNg 64
#define BKg 32
#define LDSK 36
#define A_TILE_B (BMg*LDSK*4)       /* 18432 */
#define B_TILE_B (BNg*LDSK*4)       /*  9216 */
#define OFF_AR 0
#define OFF_AI (A_TILE_B)
#define OFF_AS (2*A_TILE_B)
#define OFF_BR (3*A_TILE_B)
#define OFF_BI (3*A_TILE_B + B_TILE_B)
#define OFF_BS (3*A_TILE_B + 2*B_TILE_B)
#define STG_BYTES (3*A_TILE_B + 3*B_TILE_B)   /* 82944 */
#define SMEM_GEMM (2*STG_BYTES)               /* 165888 */

__global__ __launch_bounds__(256, 1)
void cmma_gemm(const float* __restrict__ Ar, const float* __restrict__ Ai,
               const float* __restrict__ As,
               const float* __restrict__ Br, const float* __restrict__ Bi,
               const float* __restrict__ Bs,
               float* __restrict__ Cr, float* __restrict__ Ci,
               int M, int N, int K,
               const float* __restrict__ biasr, const float* __restrict__ biasi,
               const float* __restrict__ resr,  const float* __restrict__ resi)
{
    extern __shared__ float sm[];
    const uint32_t sb = smem_u32(sm);
    const int tid = threadIdx.x;
    const int wid = tid >> 5, lane = tid & 31;
    const int g = lane >> 2, t4 = lane & 3;
    const int wm = wid & 3, wn = wid >> 2;
    const int bm = blockIdx.y * BMg, bn = blockIdx.x * BNg;
    const int row8 = tid >> 3, c4b = (tid & 7) * 4;

    // ldmatrix per-lane offsets (bytes, relative to tile base)
    const int a_r = (lane & 7) + ((lane >> 3) & 1) * 8;
    const int a_c = (lane >> 4) * 4;
    const uint32_t a_off = (uint32_t)(((wm*32 + a_r) * LDSK + a_c) * 4);
    const int b_r = (lane & 7) + ((lane >> 4) ? 8 : 0);
    const int b_c = ((lane >> 3) & 1) * 4;
    const uint32_t b_off = (uint32_t)(((wn*32 + b_r) * LDSK + b_c) * 4);

    float aP1[2][4][4], aP2[2][4][4], aP3[2][4][4];
#pragma unroll
    for (int mt = 0; mt < 2; mt++)
#pragma unroll
        for (int nt = 0; nt < 4; nt++)
#pragma unroll
            for (int r = 0; r < 4; r++) { aP1[mt][nt][r]=0.f; aP2[mt][nt][r]=0.f; aP3[mt][nt][r]=0.f; }

    const int nch = K / BKg;
    auto prefetch = [&](int ch) {
        const uint32_t dst = sb + (uint32_t)((ch & 1) * STG_BYTES);
        const int k0 = ch * BKg;
#pragma unroll
        for (int j = 0; j < 4; j++) {
            const int row = row8 + j * 32;
            const uint32_t o = (uint32_t)((row * LDSK + c4b) * 4);
            const size_t ga = (size_t)(bm + row) * K + k0 + c4b;
            CP16(dst + OFF_AR + o, Ar + ga);
            CP16(dst + OFF_AI + o, Ai + ga);
            CP16(dst + OFF_AS + o, As + ga);
        }
#pragma unroll
        for (int j = 0; j < 2; j++) {
            const int row = row8 + j * 32;
            const uint32_t o = (uint32_t)((row * LDSK + c4b) * 4);
            const size_t gb = (size_t)(bn + row) * K + k0 + c4b;
            CP16(dst + OFF_BR + o, Br + gb);
            CP16(dst + OFF_BI + o, Bi + gb);
            CP16(dst + OFF_BS + o, Bs + gb);
        }
    };

    prefetch(0);
    CP_COMMIT();
    for (int ch = 0; ch < nch; ch++) {
        if (ch + 1 < nch) prefetch(ch + 1);
        CP_COMMIT();
        CP_WAIT1();
        __syncthreads();
        const uint32_t su = sb + (uint32_t)((ch & 1) * STG_BYTES);
#pragma unroll
        for (int ks = 0; ks < 4; ks++) {
            const uint32_t ko = (uint32_t)(ks * 32);   // 8 floats
            uint32_t a1[2][4], a2[2][4], a3[2][4];
#pragma unroll
            for (int mt = 0; mt < 2; mt++) {
                const uint32_t ao = su + a_off + (uint32_t)(mt * 16 * LDSK * 4) + ko;
                LDSM4(a1[mt], ao + OFF_AR);
                LDSM4(a2[mt], ao + OFF_AI);
                LDSM4(a3[mt], ao + OFF_AS);
            }
            uint32_t br_[4][2], bi_[4][2], bs_[4][2];
#pragma unroll
            for (int ntp = 0; ntp < 2; ntp++) {
                const uint32_t bo = su + b_off + (uint32_t)(ntp * 16 * LDSK * 4) + ko;
                uint32_t t[4];
                LDSM4(t, bo + OFF_BR);
                br_[2*ntp][0]=t[0]; br_[2*ntp][1]=t[1]; br_[2*ntp+1][0]=t[2]; br_[2*ntp+1][1]=t[3];
                LDSM4(t, bo + OFF_BI);
                bi_[2*ntp][0]=t[0]; bi_[2*ntp][1]=t[1]; bi_[2*ntp+1][0]=t[2]; bi_[2*ntp+1][1]=t[3];
                LDSM4(t, bo + OFF_BS);
                bs_[2*ntp][0]=t[0]; bs_[2*ntp][1]=t[1]; bs_[2*ntp+1][0]=t[2]; bs_[2*ntp+1][1]=t[3];
            }
#pragma unroll
            for (int mt = 0; mt < 2; mt++)
#pragma unroll
                for (int nt = 0; nt < 4; nt++) {
                    MMA_TF32(aP1[mt][nt], a1[mt], br_[nt]);
                    MMA_TF32(aP2[mt][nt], a2[mt], bi_[nt]);
                    MMA_TF32(aP3[mt][nt], a3[mt], bs_[nt]);
                }
        }
        __syncthreads();
    }

#pragma unroll
    for (int mt = 0; mt < 2; mt++) {
#pragma unroll
        for (int rh = 0; rh < 2; rh++) {
            const int row = bm + wm*32 + mt*16 + g + rh*8;
#pragma unroll
            for (int nt = 0; nt < 4; nt++) {
                const int col = bn + wn*32 + nt*8 + 2*t4;
                float p1a = aP1[mt][nt][rh*2],  p1b = aP1[mt][nt][rh*2+1];
                float p2a = aP2[mt][nt][rh*2],  p2b = aP2[mt][nt][rh*2+1];
                float p3a = aP3[mt][nt][rh*2],  p3b = aP3[mt][nt][rh*2+1];
                float vr0 = p1a - p2a, vr1 = p1b - p2b;
                float vi0 = p3a - p1a - p2a, vi1 = p3b - p1b - p2b;
                if (biasr) {
                    vr0 += biasr[col]; vr1 += biasr[col+1];
                    vi0 += biasi[col]; vi1 += biasi[col+1];
                }
                if (resr) {
                    const float2 rr = *(const float2*)(resr + (size_t)row*N + col);
                    const float2 ri = *(const float2*)(resi + (size_t)row*N + col);
                    vr0 += rr.x; vr1 += rr.y; vi0 += ri.x; vi1 += ri.y;
                }
                *(float2*)(Cr + (size_t)row*N + col) = make_float2(vr0, vr1);
                *(float2*)(Ci + (size_t)row*N + col) = make_float2(vi0, vi1);
            }
        }
    }
}

// ================= scores: S = (QrKr^T + QiKi^T)*SCALE (cp.async+ldmatrix) ==
#define LDSQ 68
#define QTILE_B (128*LDSQ*4)
#define SMEM_SC (4*QTILE_B)   /* 139264 B */

__global__ __launch_bounds__(256, 1)
void scores_mma(const float* __restrict__ Q_r, const float* __restrict__ Q_i,
                const float* __restrict__ K_r, const float* __restrict__ K_i,
                float* __restrict__ S)
{
    if (blockIdx.x > blockIdx.y) return;
    const int bh = blockIdx.z;
    const int bm = blockIdx.y * 128, bn = blockIdx.x * 128;
    const size_t off = (size_t)(bh >> 4) * Ln * Dn + (size_t)(bh & 15) * HDn;
    extern __shared__ float sm[];
    const uint32_t sb = smem_u32(sm);

    const int tid = threadIdx.x;
    const int wid = tid >> 5, lane = tid & 31;
    const int g = lane >> 2, t4 = lane & 3;
    const int wm = wid & 3, wn = wid >> 2;       // warp tile 32x64

    // stage all four 128x64 tiles via cp.async (q/k are pre-rounded by rope)
#pragma unroll
    for (int j = 0; j < 8; j++) {
        const int f = tid + j * 256;
        const int row = f >> 4, c4 = (f & 15) * 4;
        const uint32_t o = (uint32_t)((row * LDSQ + c4) * 4);
        const size_t gq = off + (size_t)(bm + row) * Dn + c4;
        const size_t gk = off + (size_t)(bn + row) * Dn + c4;
        CP16(sb + 0*QTILE_B + o, Q_r + gq);
        CP16(sb + 1*QTILE_B + o, Q_i + gq);
        CP16(sb + 2*QTILE_B + o, K_r + gk);
        CP16(sb + 3*QTILE_B + o, K_i + gk);
    }
    CP_COMMIT();
    CP_WAIT0();
    __syncthreads();

    const int a_r = (lane & 7) + ((lane >> 3) & 1) * 8;
    const int a_c = (lane >> 4) * 4;
    const uint32_t a_off = (uint32_t)(((wm*32 + a_r) * LDSQ + a_c) * 4);
    const int b_r = (lane & 7) + ((lane >> 4) ? 8 : 0);
    const int b_c = ((lane >> 3) & 1) * 4;
    const uint32_t b_off = (uint32_t)(((wn*64 + b_r) * LDSQ + b_c) * 4);

    float acc[2][8][4];
#pragma unroll
    for (int mt = 0; mt < 2; mt++)
#pragma unroll
        for (int nt = 0; nt < 8; nt++)
#pragma unroll
            for (int r = 0; r < 4; r++) acc[mt][nt][r] = 0.f;

#pragma unroll
    for (int ks = 0; ks < 8; ks++) {
        const uint32_t ko = (uint32_t)(ks * 32);
        uint32_t aqr[2][4], aqi[2][4];
#pragma unroll
        for (int mt = 0; mt < 2; mt++) {
            const uint32_t ao = sb + a_off + (uint32_t)(mt * 16 * LDSQ * 4) + ko;
            LDSM4(aqr[mt], ao + 0*QTILE_B);
            LDSM4(aqi[mt], ao + 1*QTILE_B);
        }
        uint32_t bkr[8][2], bki[8][2];
#pragma unroll
        for (int ntp = 0; ntp < 4; ntp++) {
            const uint32_t bo = sb + b_off + (uint32_t)(ntp * 16 * LDSQ * 4) + ko;
            uint32_t t[4];
            LDSM4(t, bo + 2*QTILE_B);
            bkr[2*ntp][0]=t[0]; bkr[2*ntp][1]=t[1]; bkr[2*ntp+1][0]=t[2]; bkr[2*ntp+1][1]=t[3];
            LDSM4(t, bo + 3*QTILE_B);
            bki[2*ntp][0]=t[0]; bki[2*ntp][1]=t[1]; bki[2*ntp+1][0]=t[2]; bki[2*ntp+1][1]=t[3];
        }
#pragma unroll
        for (int mt = 0; mt < 2; mt++)
#pragma unroll
            for (int nt = 0; nt < 8; nt++) {
                MMA_TF32(acc[mt][nt], aqr[mt], bkr[nt]);
                MMA_TF32(acc[mt][nt], aqi[mt], bki[nt]);
            }
    }

#pragma unroll
    for (int mt = 0; mt < 2; mt++) {
#pragma unroll
        for (int rh = 0; rh < 2; rh++) {
            const int row = bm + wm*32 + mt*16 + g + rh*8;
#pragma unroll
            for (int nt = 0; nt < 8; nt++) {
                const int col = bn + wn*64 + nt*8 + 2*t4;
                *(float2*)(S + ((size_t)bh * Ln + row) * Ln + col) =
                    make_float2(acc[mt][nt][rh*2] * SCALEc, acc[mt][nt][rh*2+1] * SCALEc);
            }
        }
    }
}

// ================= AV: O = P @ V (r,i) + rounded outputs + sum ==============
#define LDSP 36
#define LDSV 36
__global__ __launch_bounds__(256, 2)
void av_mma(const float* __restrict__ S,
            const float* __restrict__ V_r, const float* __restrict__ V_i,
            float* __restrict__ Or, float* __restrict__ Oi, float* __restrict__ Os)
{
    const int bh = blockIdx.z;
    const int bm = blockIdx.y * 128;
    const float* P = S + (size_t)bh * Ln * Ln;
    const size_t voff = (size_t)(bh >> 4) * Ln * Dn + (size_t)(bh & 15) * HDn;

    __shared__ float Ps[128*LDSP];
    __shared__ float Vtr[64*LDSV], Vti[64*LDSV];
    const uint32_t ps_b  = smem_u32(Ps);
    const uint32_t vtr_b = smem_u32(Vtr);
    const uint32_t vti_b = smem_u32(Vti);

    const int tid = threadIdx.x;
    const int wid = tid >> 5, lane = tid & 31;
    const int g = lane >> 2, t4 = lane & 3;
    const int wm = wid & 3, wn = wid >> 2;

    const int a_r = (lane & 7) + ((lane >> 3) & 1) * 8;
    const int a_c = (lane >> 4) * 4;
    const uint32_t a_off = (uint32_t)(((wm*32 + a_r) * LDSP + a_c) * 4);
    const int b_r = (lane & 7) + ((lane >> 4) ? 8 : 0);
    const int b_c = ((lane >> 3) & 1) * 4;
    const uint32_t b_off = (uint32_t)(((wn*32 + b_r) * LDSV + b_c) * 4);

    float accR[2][4][4], accI[2][4][4];
#pragma unroll
    for (int mt = 0; mt < 2; mt++)
#pragma unroll
        for (int nt = 0; nt < 4; nt++)
#pragma unroll
            for (int r = 0; r < 4; r++) { accR[mt][nt][r] = 0.f; accI[mt][nt][r] = 0.f; }

    const int kmax = bm + 128;
    for (int k0 = 0; k0 < kmax; k0 += 32) {
        // stage P via cp.async (softmax wrote rounded values)
#pragma unroll
        for (int j = 0; j < 4; j++) {
            const int f = tid + j * 256;
            const int row = f >> 3, c4 = (f & 7) * 4;
            CP16(ps_b + (uint32_t)((row * LDSP + c4) * 4),
                 P + (size_t)(bm + row) * Ln + k0 + c4);
        }
        CP_COMMIT();
        // stage V transposed with rna conversion
#pragma unroll
        for (int j = 0; j < 2; j++) {
            const int f = tid + j * 256;
            const int kr = f >> 4, c4 = (f & 15) * 4;
            const float4 vr = *(const float4*)(V_r + voff + (size_t)(k0 + kr) * Dn + c4);
            const float4 vi = *(const float4*)(V_i + voff + (size_t)(k0 + kr) * Dn + c4);
            Vtr[(c4+0)*LDSV + kr] = rnaf(vr.x);
            Vtr[(c4+1)*LDSV + kr] = rnaf(vr.y);
            Vtr[(c4+2)*LDSV + kr] = rnaf(vr.z);
            Vtr[(c4+3)*LDSV + kr] = rnaf(vr.w);
            Vti[(c4+0)*LDSV + kr] = rnaf(vi.x);
            Vti[(c4+1)*LDSV + kr] = rnaf(vi.y);
            Vti[(c4+2)*LDSV + kr] = rnaf(vi.z);
            Vti[(c4+3)*LDSV + kr] = rnaf(vi.w);
        }
        CP_WAIT0();
        __syncthreads();
#pragma unroll
        for (int ks = 0; ks < 4; ks++) {
            const uint32_t ko = (uint32_t)(ks * 32);
            uint32_t af[2][4];
#pragma unroll
            for (int mt = 0; mt < 2; mt++)
                LDSM4(af[mt], ps_b + a_off + (uint32_t)(mt * 16 * LDSP * 4) + ko);
            uint32_t bvr[4][2], bvi[4][2];
#pragma unroll
            for (int ntp = 0; ntp < 2; ntp++) {
                const uint32_t bo = b_off + (uint32_t)(ntp * 16 * LDSV * 4) + ko;
                uint32_t t[4];
                LDSM4(t, vtr_b + bo);
                bvr[2*ntp][0]=t[0]; bvr[2*ntp][1]=t[1]; bvr[2*ntp+1][0]=t[2]; bvr[2*ntp+1][1]=t[3];
                LDSM4(t, vti_b + bo);
                bvi[2*ntp][0]=t[0]; bvi[2*ntp][1]=t[1]; bvi[2*ntp+1][0]=t[2]; bvi[2*ntp+1][1]=t[3];
            }
#pragma unroll
            for (int mt = 0; mt < 2; mt++)
#pragma unroll
                for (int nt = 0; nt < 4; nt++) {
                    MMA_TF32(accR[mt][nt], af[mt], bvr[nt]);
                    MMA_TF32(accI[mt][nt], af[mt], bvi[nt]);
                }
        }
        __syncthreads();
    }

#pragma unroll
    for (int mt = 0; mt < 2; mt++) {
#pragma unroll
        for (int rh = 0; rh < 2; rh++) {
            const int row = bm + wm*32 + mt*16 + g + rh*8;
#pragma unroll
            for (int nt = 0; nt < 4; nt++) {
                const int col = wn*32 + nt*8 + 2*t4;
                const size_t o0 = voff + (size_t)row*Dn + col;
                float r0 = rnaf(accR[mt][nt][rh*2]),  r1 = rnaf(accR[mt][nt][rh*2+1]);
                float i0 = rnaf(accI[mt][nt][rh*2]),  i1 = rnaf(accI[mt][nt][rh*2+1]);
                *(float2*)(Or + o0) = make_float2(r0, r1);
                *(float2*)(Oi + o0) = make_float2(i0, i1);
                *(float2*)(Os + o0) = make_float2(rnaf(r0 + i0), rnaf(r1 + i1));
            }
        }
    }
}

// ---------------- complex layernorm (rounded outputs + sum) -----------------
__global__ void cln_kernel(const float* __restrict__ xr, const float* __restrict__ xi,
                           const float* __restrict__ gr, const float* __restrict__ gi,
                           const float* __restrict__ bre, const float* __restrict__ bim,
                           float* __restrict__ outr, float* __restrict__ outi,
                           float* __restrict__ outs)
{
    int row = blockIdx.x;
    const float* pr = xr + (size_t)row * Dn;
    const float* pi = xi + (size_t)row * Dn;
    __shared__ float s1[256], s2[256];
    int tid = threadIdx.x;
    float sr = 0.f, si = 0.f;
    for (int j = tid; j < Dn; j += 256) { sr += pr[j]; si += pi[j]; }
    s1[tid] = sr; s2[tid] = si;
    __syncthreads();
    for (int o = 128; o > 0; o >>= 1) {
        if (tid < o) { s1[tid] += s1[tid+o]; s2[tid] += s2[tid+o]; }
        __syncthreads();
    }
    float mr = s1[0] * (1.f/Dn), mi = s2[0] * (1.f/Dn);
    __syncthreads();
    float v = 0.f;
    for (int j = tid; j < Dn; j += 256) {
        float cr = pr[j] - mr, ci = pi[j] - mi;
        v += cr*cr + ci*ci;
    }
    s1[tid] = v;
    __syncthreads();
    for (int o = 128; o > 0; o >>= 1) {
        if (tid < o) s1[tid] += s1[tid+o];
        __syncthreads();
    }
    float inv = rsqrtf(s1[0] * (1.f/Dn) + EPSc);
    for (int j = tid; j < Dn; j += 256) {
        float nr = (pr[j]-mr)*inv, ni = (pi[j]-mi)*inv;
        float vr = rnaf(nr*gr[j] - ni*gi[j] + bre[j]);
        float vi = rnaf(nr*gi[j] + ni*gr[j] + bim[j]);
        outr[(size_t)row*Dn + j] = vr;
        outi[(size_t)row*Dn + j] = vi;
        outs[(size_t)row*Dn + j] = rnaf(vr + vi);
    }
}

// ---------------- RoPE (in place, rounded outputs) --------------------------
__global__ void rope_kernel(float* __restrict__ xr, float* __restrict__ xi)
{
    int idx = blockIdx.x * blockDim.x + threadIdx.x;
    int j = idx & 31;
    int t = idx >> 5;
    int h = t & (Hn-1); t >>= 4;
    int l = t & (Ln-1);
    int b = t >> 10;
    size_t base = ((size_t)(b*Ln + l)) * Dn + h * HDn;
    double invf = exp(-((double)(2*j) / (double)HDn) * 9.210340371976184);
    double th = (double)l * invf;
    double sd, cd;
    sincos(th, &sd, &cd);
    float c = (float)cd, s = (float)sd;
    float a0 = xr[base+j], a1 = xr[base+j+32];
    xr[base+j]    = rnaf(a0*c - a1*s);
    xr[base+j+32] = rnaf(a1*c + a0*s);
    float b0 = xi[base+j], b1 = xi[base+j+32];
    xi[base+j]    = rnaf(b0*c - b1*s);
    xi[base+j+32] = rnaf(b1*c + b0*s);
}

// ---------------- causal softmax (rounded), zeroed up to tile edge ----------
__global__ void softmax_kernel(float* __restrict__ S)
{
    int row = blockIdx.x;
    int l = row & (Ln - 1);
    float* p = S + (size_t)row * Ln;
    __shared__ float red[256];
    int tid = threadIdx.x;
    float m = -1e30f;
    for (int j = tid; j <= l; j += 256) m = fmaxf(m, p[j]);
    red[tid] = m; __syncthreads();
    for (int o = 128; o > 0; o >>= 1) {
        if (tid < o) red[tid] = fmaxf(red[tid], red[tid+o]);
        __syncthreads();
    }
    m = red[0]; __syncthreads();
    float s = 0.f;
    for (int j = tid; j <= l; j += 256) s += expf(p[j] - m);
    red[tid] = s; __syncthreads();
    for (int o = 128; o > 0; o >>= 1) {
        if (tid < o) red[tid] += red[tid+o];
        __syncthreads();
    }
    float inv = 1.f / red[0];
    const int lim = (l & ~127) + 128;
    for (int j = tid; j < lim; j += 256)
        p[j] = (j <= l) ? rnaf(expf(p[j] - m) * inv) : 0.f;
}

// ---------------- ModReLU (rounded outputs + sum) ---------------------------
__global__ void modrelu_kernel(float* __restrict__ fr, float* __restrict__ fi,
                               float* __restrict__ fs, const float* __restrict__ mb)
{
    size_t idx = (size_t)blockIdx.x * blockDim.x + threadIdx.x;
    int col = (int)(idx & (HIDn - 1));
    float r = fr[idx], i = fi[idx];
    float mag = sqrtf(r*r + i*i);
    float safe = mag > 0.f ? mag : 1.f;
    float act = fmaxf(mag + mb[col], 0.f);
    float fac = act / safe;
    float ur = rnaf(r * fac), ui = rnaf(i * fac);
    fr[idx] = ur;
    fi[idx] = ui;
    fs[idx] = rnaf(ur + ui);
}

// ---------------- launch ----------------------------------------------------
extern "C" void kernel_launch(void* const* d_in, const int* in_sizes, int n_in,
                              void* d_out, int out_size)
{
    const float* x_r   = (const float*)d_in[0];
    const float* x_i   = (const float*)d_in[1];
    const float* Wq_r  = (const float*)d_in[2];
    const float* Wq_i  = (const float*)d_in[3];
    const float* Wk_r  = (const float*)d_in[4];
    const float* Wk_i  = (const float*)d_in[5];
    const float* Wv_r  = (const float*)d_in[6];
    const float* Wv_i  = (const float*)d_in[7];
    const float* Wo_r  = (const float*)d_in[8];
    const float* Wo_i  = (const float*)d_in[9];
    const float* bo_r  = (const float*)d_in[10];
    const float* bo_i  = (const float*)d_in[11];
    const float* ln1_gr = (const float*)d_in[12];
    const float* ln1_gi = (const float*)d_in[13];
    const float* ln1_br = (const float*)d_in[14];
    const float* ln1_bi = (const float*)d_in[15];
    const float* ln2_gr = (const float*)d_in[16];
    const float* ln2_gi = (const float*)d_in[17];
    const float* ln2_br = (const float*)d_in[18];
    const float* ln2_bi = (const float*)d_in[19];
    const float* W1_r  = (const float*)d_in[20];
    const float* W1_i  = (const float*)d_in[21];
    const float* b1_r  = (const float*)d_in[22];
    const float* b1_i  = (const float*)d_in[23];
    const float* W2_r  = (const float*)d_in[24];
    const float* W2_i  = (const float*)d_in[25];
    const float* b2_r  = (const float*)d_in[26];
    const float* b2_i  = (const float*)d_in[27];
    const float* mod_b = (const float*)d_in[28];
    float* out = (float*)d_out;

    float *hr, *hi, *hs, *qr, *qi, *kr, *ki, *vr, *vi, *sbuf;
    float *aor, *aoi, *aos, *ar, *ai, *fr, *fi, *fs;
    float *wqr, *wqi, *wqs, *wkr, *wki, *wks, *wvr, *wvi, *wvs;
    float *wor, *woi, *wos, *w1r, *w1i, *w1s, *w2r, *w2i, *w2s;
    cudaGetSymbolAddress((void**)&hr,  g_hr);
    cudaGetSymbolAddress((void**)&hi,  g_hi);
    cudaGetSymbolAddress((void**)&hs,  g_hs);
    cudaGetSymbolAddress((void**)&qr,  g_qr);
    cudaGetSymbolAddress((void**)&qi,  g_qi);
    cudaGetSymbolAddress((void**)&kr,  g_kr);
    cudaGetSymbolAddress((void**)&ki,  g_ki);
    cudaGetSymbolAddress((void**)&vr,  g_vr);
    cudaGetSymbolAddress((void**)&vi,  g_vi);
    cudaGetSymbolAddress((void**)&sbuf, g_s);
    cudaGetSymbolAddress((void**)&aor, g_aor);
    cudaGetSymbolAddress((void**)&aoi, g_aoi);
    cudaGetSymbolAddress((void**)&aos, g_aos);
    cudaGetSymbolAddress((void**)&ar,  g_ar);
    cudaGetSymbolAddress((void**)&ai,  g_ai);
    cudaGetSymbolAddress((void**)&fr,  g_fr);
    cudaGetSymbolAddress((void**)&fi,  g_fi);
    cudaGetSymbolAddress((void**)&fs,  g_fs);
    cudaGetSymbolAddress((void**)&wqr, g_wq_r); cudaGetSymbolAddress((void**)&wqi, g_wq_i); cudaGetSymbolAddress((void**)&wqs, g_wq_s);
    cudaGetSymbolAddress((void**)&wkr, g_wk_r); cudaGetSymbolAddress((void**)&wki, g_wk_i); cudaGetSymbolAddress((void**)&wks, g_wk_s);
    cudaGetSymbolAddress((void**)&wvr, g_wv_r); cudaGetSymbolAddress((void**)&wvi, g_wv_i); cudaGetSymbolAddress((void**)&wvs, g_wv_s);
    cudaGetSymbolAddress((void**)&wor, g_wo_r); cudaGetSymbolAddress((void**)&woi, g_wo_i); cudaGetSymbolAddress((void**)&wos, g_wo_s);
    cudaGetSymbolAddress((void**)&w1r, g_w1_r); cudaGetSymbolAddress((void**)&w1i, g_w1_i); cudaGetSymbolAddress((void**)&w1s, g_w1_s);
    cudaGetSymbolAddress((void**)&w2r, g_w2_r); cudaGetSymbolAddress((void**)&w2i, g_w2_i); cudaGetSymbolAddress((void**)&w2s, g_w2_s);

    cudaFuncSetAttribute(cmma_gemm,  cudaFuncAttributeMaxDynamicSharedMemorySize, SMEM_GEMM);
    cudaFuncSetAttribute(scores_mma, cudaFuncAttributeMaxDynamicSharedMemorySize, SMEM_SC);

    // 0. weight prep (rounded copies + Gauss sums)
    const int n4d = Dn*Dn/4, n4h = HIDn*Dn/4;
    wprep_kernel<<<n4d/256, 256>>>((const float4*)Wq_r, (const float4*)Wq_i, (float4*)wqr, (float4*)wqi, (float4*)wqs, n4d);
    wprep_kernel<<<n4d/256, 256>>>((const float4*)Wk_r, (const float4*)Wk_i, (float4*)wkr, (float4*)wki, (float4*)wks, n4d);
    wprep_kernel<<<n4d/256, 256>>>((const float4*)Wv_r, (const float4*)Wv_i, (float4*)wvr, (float4*)wvi, (float4*)wvs, n4d);
    wprep_kernel<<<n4d/256, 256>>>((const float4*)Wo_r, (const float4*)Wo_i, (float4*)wor, (float4*)woi, (float4*)wos, n4d);
    wprep_kernel<<<n4h/256, 256>>>((const float4*)W1_r, (const float4*)W1_i, (float4*)w1r, (float4*)w1i, (float4*)w1s, n4h);
    wprep_kernel<<<n4h/256, 256>>>((const float4*)W2_r, (const float4*)W2_i, (float4*)w2r, (float4*)w2i, (float4*)w2s, n4h);

    // 1. LN1
    cln_kernel<<<Mn, 256>>>(x_r, x_i, ln1_gr, ln1_gi, ln1_br, ln1_bi, hr, hi, hs);

    // 2. QKV projections
    dim3 gproj(Dn/BNg, Mn/BMg);
    cmma_gemm<<<gproj, 256, SMEM_GEMM>>>(hr, hi, hs, wqr, wqi, wqs, qr, qi, Mn, Dn, Dn, nullptr, nullptr, nullptr, nullptr);
    cmma_gemm<<<gproj, 256, SMEM_GEMM>>>(hr, hi, hs, wkr, wki, wks, kr, ki, Mn, Dn, Dn, nullptr, nullptr, nullptr, nullptr);
    cmma_gemm<<<gproj, 256, SMEM_GEMM>>>(hr, hi, hs, wvr, wvi, wvs, vr, vi, Mn, Dn, Dn, nullptr, nullptr, nullptr, nullptr);

    // 3. RoPE on Q and K (rounded)
    rope_kernel<<<(Bn*Ln*Hn*32)/256, 256>>>(qr, qi);
    rope_kernel<<<(Bn*Ln*Hn*32)/256, 256>>>(kr, ki);

    // 4. attention
    scores_mma<<<dim3(Ln/128, Ln/128, Bn*Hn), 256, SMEM_SC>>>(qr, qi, kr, ki, sbuf);
    softmax_kernel<<<Bn*Hn*Ln, 256>>>(sbuf);
    av_mma<<<dim3(1, Ln/128, Bn*Hn), 256>>>(sbuf, vr, vi, aor, aoi, aos);

    // 5. out projection + bias + residual(x)
    cmma_gemm<<<gproj, 256, SMEM_GEMM>>>(aor, aoi, aos, wor, woi, wos, ar, ai, Mn, Dn, Dn, bo_r, bo_i, x_r, x_i);

    // 6. LN2
    cln_kernel<<<Mn, 256>>>(ar, ai, ln2_gr, ln2_gi, ln2_br, ln2_bi, hr, hi, hs);

    // 7. FC1 + bias
    cmma_gemm<<<dim3(HIDn/BNg, Mn/BMg), 256, SMEM_GEMM>>>(hr, hi, hs, w1r, w1i, w1s, fr, fi, Mn, HIDn, Dn, b1_r, b1_i, nullptr, nullptr);

    // 8. ModReLU (rounded + sum)
    modrelu_kernel<<<(Mn*(size_t)HIDn)/256, 256>>>(fr, fi, fs, mod_b);

    // 9. FC2 + bias + residual(ar/ai) -> output
    cmma_gemm<<<gproj, 256, SMEM_GEMM>>>(fr, fi, fs, w2r, w2i, w2s, out, out + (size_t)Mn*Dn, Mn, Dn, HIDn, b2_r, b2_i, ar, ai);
}

// round 11
// speedup vs baseline: 1.2015x; 1.2015x over previous
#include <cuda_runtime.h>
#include <cstdint>
#include <math.h>

#define Bn   2
#define Ln   1024
#define Dn   1024
#define Hn   16
#define HDn  64
#define HIDn 4096
#define Mn   (Bn*Ln)        /* 2048 rows */
#define EPSc 1e-6f
#define SCALEc 0.125f       /* 64^-0.5 */

// ---------------- scratch (device globals; no runtime allocation) ----------
__device__ float g_hr[Mn*Dn],  g_hi[Mn*Dn];
__device__ float g_qr[Mn*Dn],  g_qi[Mn*Dn];
__device__ float g_kr[Mn*Dn],  g_ki[Mn*Dn];
__device__ float g_vr[Mn*Dn],  g_vi[Mn*Dn];
__device__ float g_s [Bn*Hn*Ln*Ln];          /* 128 MB scores/attn */
__device__ float g_aor[Mn*Dn], g_aoi[Mn*Dn];
__device__ float g_ar[Mn*Dn],  g_ai[Mn*Dn];
__device__ float g_fr[Mn*HIDn], g_fi[Mn*HIDn];

// ================= helpers (baseline PTX only) ==============================
__device__ __forceinline__ uint32_t smem_u32(const void* p) {
    uint32_t a;
    asm("{ .reg .u64 t; cvta.to.shared.u64 t, %1; cvt.u32.u64 %0, t; }" : "=r"(a) : "l"(p));
    return a;
}
#define CP16(dst_u32, src_ptr) \
    asm volatile("cp.async.cg.shared.global [%0], [%1], 16;" :: "r"(dst_u32), "l"(src_ptr) : "memory")
#define CP_COMMIT() asm volatile("cp.async.commit_group;" ::: "memory")
#define CP_WAIT1()  asm volatile("cp.async.wait_group 1;" ::: "memory")
#define CP_WAIT0()  asm volatile("cp.async.wait_group 0;" ::: "memory")

__device__ __forceinline__ uint32_t f2tf32(float x) {
    uint32_t r;
    asm("cvt.rna.tf32.f32 %0, %1;" : "=r"(r) : "f"(x));
    return r;
}
__device__ __forceinline__ float rnaf(float x) { return __uint_as_float(f2tf32(x)); }

#define MMA_TF32(d, a, b) \
    asm volatile("mma.sync.aligned.m16n8k8.row.col.f32.tf32.tf32.f32 " \
        "{%0,%1,%2,%3}, {%4,%5,%6,%7}, {%8,%9}, {%0,%1,%2,%3};" \
        : "+f"((d)[0]), "+f"((d)[1]), "+f"((d)[2]), "+f"((d)[3]) \
        : "r"((a)[0]), "r"((a)[1]), "r"((a)[2]), "r"((a)[3]), \
          "r"((b)[0]), "r"((b)[1]))

#define LDSM4(r, addr) \
    asm volatile("ldmatrix.sync.aligned.m8n8.x4.shared.b16 {%0,%1,%2,%3}, [%4];" \
        : "=r"((r)[0]), "=r"((r)[1]), "=r"((r)[2]), "=r"((r)[3]) : "r"(addr))

// ================= complex GEMM, cp.async + ldmatrix, 2 CTA/SM ==============
// C = A @ B^T (complex). A:[M,K], B:[N,K] row-major fp32.
// Block 128x64, BK=32, 8 warps (4m x 2n), warp tile 32x32.
//   accR += Ar*Br + (-Ai)*Bi ;  accI += Ar*Bi + Ai*Br
#define BMg 128
#define BNg 64
#define BKg 32
#define LDSK 36
#define A_TILE_B (BMg*LDSK*4)       /* 18432 */
#define B_TILE_B (BNg*LDSK*4)       /*  9216 */
#define OFF_AR 0
#define OFF_AI (A_TILE_B)
#define OFF_BR (2*A_TILE_B)
#define OFF_BI (2*A_TILE_B + B_TILE_B)
#define STG_BYTES (2*A_TILE_B + 2*B_TILE_B)   /* 55296 */
#define SMEM_GEMM (2*STG_BYTES)               /* 110592 */

__global__ __launch_bounds__(256, 2)
void cmma_gemm(const float* __restrict__ Ar, const float* __restrict__ Ai,
               const float* __restrict__ Br, const float* __restrict__ Bi,
               float* __restrict__ Cr, float* __restrict__ Ci,
               int M, int N, int K,
               const float* __restrict__ biasr, const float* __restrict__ biasi,
               const float* __restrict__ resr,  const float* __restrict__ resi)
{
    extern __shared__ float sm[];
    const uint32_t sb = smem_u32(sm);
    const int tid = threadIdx.x;
    const int wid = tid >> 5, lane = tid & 31;
    const int g = lane >> 2, t4 = lane & 3;
    const int wm = wid & 3, wn = wid >> 2;
    const int bm = blockIdx.y * BMg, bn = blockIdx.x * BNg;
    const int row8 = tid >> 3, c4b = (tid & 7) * 4;

    // ldmatrix per-lane offsets (bytes, relative to tile base) — validated R8
    const int a_r = (lane & 7) + ((lane >> 3) & 1) * 8;
    const int a_c = (lane >> 4) * 4;
    const uint32_t a_off = (uint32_t)(((wm*32 + a_r) * LDSK + a_c) * 4);
    const int b_r = (lane & 7) + ((lane >> 4) ? 8 : 0);
    const int b_c = ((lane >> 3) & 1) * 4;
    const uint32_t b_off = (uint32_t)(((wn*32 + b_r) * LDSK + b_c) * 4);

    float accR[2][4][4], accI[2][4][4];
#pragma unroll
    for (int mt = 0; mt < 2; mt++)
#pragma unroll
        for (int nt = 0; nt < 4; nt++)
#pragma unroll
            for (int r = 0; r < 4; r++) { accR[mt][nt][r] = 0.f; accI[mt][nt][r] = 0.f; }

    const int nch = K / BKg;
    auto prefetch = [&](int ch) {
        const uint32_t dst = sb + (uint32_t)((ch & 1) * STG_BYTES);
        const int k0 = ch * BKg;
#pragma unroll
        for (int j = 0; j < 4; j++) {
            const int row = row8 + j * 32;
            const uint32_t o = (uint32_t)((row * LDSK + c4b) * 4);
            const size_t ga = (size_t)(bm + row) * K + k0 + c4b;
            CP16(dst + OFF_AR + o, Ar + ga);
            CP16(dst + OFF_AI + o, Ai + ga);
        }
#pragma unroll
        for (int j = 0; j < 2; j++) {
            const int row = row8 + j * 32;
            const uint32_t o = (uint32_t)((row * LDSK + c4b) * 4);
            const size_t gb = (size_t)(bn + row) * K + k0 + c4b;
            CP16(dst + OFF_BR + o, Br + gb);
            CP16(dst + OFF_BI + o, Bi + gb);
        }
    };

    prefetch(0);
    CP_COMMIT();
    for (int ch = 0; ch < nch; ch++) {
        if (ch + 1 < nch) prefetch(ch + 1);
        CP_COMMIT();
        CP_WAIT1();
        __syncthreads();
        const uint32_t su = sb + (uint32_t)((ch & 1) * STG_BYTES);
#pragma unroll
        for (int ks = 0; ks < 4; ks++) {
            const uint32_t ko = (uint32_t)(ks * 32);   // 8 floats
            uint32_t afr[2][4], afi[2][4];
#pragma unroll
            for (int mt = 0; mt < 2; mt++) {
                const uint32_t ao = su + a_off + (uint32_t)(mt * 16 * LDSK * 4) + ko;
                LDSM4(afr[mt], ao + OFF_AR);
                LDSM4(afi[mt], ao + OFF_AI);
            }
            uint32_t br_[4][2], bi_[4][2];
#pragma unroll
            for (int ntp = 0; ntp < 2; ntp++) {
                const uint32_t bo = su + b_off + (uint32_t)(ntp * 16 * LDSK * 4) + ko;
                uint32_t t[4];
                LDSM4(t, bo + OFF_BR);
                br_[2*ntp][0]=t[0]; br_[2*ntp][1]=t[1]; br_[2*ntp+1][0]=t[2]; br_[2*ntp+1][1]=t[3];
                LDSM4(t, bo + OFF_BI);
                bi_[2*ntp][0]=t[0]; bi_[2*ntp][1]=t[1]; bi_[2*ntp+1][0]=t[2]; bi_[2*ntp+1][1]=t[3];
            }
#pragma unroll
            for (int mt = 0; mt < 2; mt++) {
                uint32_t afn[4];
#pragma unroll
                for (int r = 0; r < 4; r++) afn[r] = afi[mt][r] ^ 0x80000000u;
#pragma unroll
                for (int nt = 0; nt < 4; nt++) {
                    MMA_TF32(accR[mt][nt], afr[mt], br_[nt]);
                    MMA_TF32(accR[mt][nt], afn,     bi_[nt]);
                    MMA_TF32(accI[mt][nt], afr[mt], bi_[nt]);
                    MMA_TF32(accI[mt][nt], afi[mt], br_[nt]);
                }
            }
        }
        __syncthreads();
    }

#pragma unroll
    for (int mt = 0; mt < 2; mt++) {
#pragma unroll
        for (int rh = 0; rh < 2; rh++) {
            const int row = bm + wm*32 + mt*16 + g + rh*8;
#pragma unroll
            for (int nt = 0; nt < 4; nt++) {
                const int col = bn + wn*32 + nt*8 + 2*t4;
                float vr0 = accR[mt][nt][rh*2],   vr1 = accR[mt][nt][rh*2+1];
                float vi0 = accI[mt][nt][rh*2],   vi1 = accI[mt][nt][rh*2+1];
                if (biasr) {
                    vr0 += biasr[col]; vr1 += biasr[col+1];
                    vi0 += biasi[col]; vi1 += biasi[col+1];
                }
                if (resr) {
                    const float2 rr = *(const float2*)(resr + (size_t)row*N + col);
                    const float2 ri = *(const float2*)(resi + (size_t)row*N + col);
                    vr0 += rr.x; vr1 += rr.y; vi0 += ri.x; vi1 += ri.y;
                }
                *(float2*)(Cr + (size_t)row*N + col) = make_float2(vr0, vr1);
                *(float2*)(Ci + (size_t)row*N + col) = make_float2(vi0, vi1);
            }
        }
    }
}

// ================= scores: S = (QrKr^T + QiKi^T)*SCALE (cp.async+ldmatrix) ==
#define LDSQ 68
#define QTILE_B (128*LDSQ*4)
#define SMEM_SC (4*QTILE_B)   /* 139264 B */

__global__ __launch_bounds__(256, 1)
void scores_mma(const float* __restrict__ Q_r, const float* __restrict__ Q_i,
                const float* __restrict__ K_r, const float* __restrict__ K_i,
                float* __restrict__ S)
{
    if (blockIdx.x > blockIdx.y) return;
    const int bh = blockIdx.z;
    const int bm = blockIdx.y * 128, bn = blockIdx.x * 128;
    const size_t off = (size_t)(bh >> 4) * Ln * Dn + (size_t)(bh & 15) * HDn;
    extern __shared__ float sm[];
    const uint32_t sb = smem_u32(sm);

    const int tid = threadIdx.x;
    const int wid = tid >> 5, lane = tid & 31;
    const int g = lane >> 2, t4 = lane & 3;
    const int wm = wid & 3, wn = wid >> 2;       // warp tile 32x64

#pragma unroll
    for (int j = 0; j < 8; j++) {
        const int f = tid + j * 256;
        const int row = f >> 4, c4 = (f & 15) * 4;
        const uint32_t o = (uint32_t)((row * LDSQ + c4) * 4);
        const size_t gq = off + (size_t)(bm + row) * Dn + c4;
        const size_t gk = off + (size_t)(bn + row) * Dn + c4;
        CP16(sb + 0*QTILE_B + o, Q_r + gq);
        CP16(sb + 1*QTILE_B + o, Q_i + gq);
        CP16(sb + 2*QTILE_B + o, K_r + gk);
        CP16(sb + 3*QTILE_B + o, K_i + gk);
    }
    CP_COMMIT();
    CP_WAIT0();
    __syncthreads();

    const int a_r = (lane & 7) + ((lane >> 3) & 1) * 8;
    const int a_c = (lane >> 4) * 4;
    const uint32_t a_off = (uint32_t)(((wm*32 + a_r) * LDSQ + a_c) * 4);
    const int b_r = (lane & 7) + ((lane >> 4) ? 8 : 0);
    const int b_c = ((lane >> 3) & 1) * 4;
    const uint32_t b_off = (uint32_t)(((wn*64 + b_r) * LDSQ + b_c) * 4);

    float acc[2][8][4];
#pragma unroll
    for (int mt = 0; mt < 2; mt++)
#pragma unroll
        for (int nt = 0; nt < 8; nt++)
#pragma unroll
            for (int r = 0; r < 4; r++) acc[mt][nt][r] = 0.f;

#pragma unroll
    for (int ks = 0; ks < 8; ks++) {
        const uint32_t ko = (uint32_t)(ks * 32);
        uint32_t aqr[2][4], aqi[2][4];
#pragma unroll
        for (int mt = 0; mt < 2; mt++) {
            const uint32_t ao = sb + a_off + (uint32_t)(mt * 16 * LDSQ * 4) + ko;
            LDSM4(aqr[mt], ao + 0*QTILE_B);
            LDSM4(aqi[mt], ao + 1*QTILE_B);
        }
        uint32_t bkr[8][2], bki[8][2];
#pragma unroll
        for (int ntp = 0; ntp < 4; ntp++) {
            const uint32_t bo = sb + b_off + (uint32_t)(ntp * 16 * LDSQ * 4) + ko;
            uint32_t t[4];
            LDSM4(t, bo + 2*QTILE_B);
            bkr[2*ntp][0]=t[0]; bkr[2*ntp][1]=t[1]; bkr[2*ntp+1][0]=t[2]; bkr[2*ntp+1][1]=t[3];
            LDSM4(t, bo + 3*QTILE_B);
            bki[2*ntp][0]=t[0]; bki[2*ntp][1]=t[1]; bki[2*ntp+1][0]=t[2]; bki[2*ntp+1][1]=t[3];
        }
#pragma unroll
        for (int mt = 0; mt < 2; mt++)
#pragma unroll
            for (int nt = 0; nt < 8; nt++) {
                MMA_TF32(acc[mt][nt], aqr[mt], bkr[nt]);
                MMA_TF32(acc[mt][nt], aqi[mt], bki[nt]);
            }
    }

#pragma unroll
    for (int mt = 0; mt < 2; mt++) {
#pragma unroll
        for (int rh = 0; rh < 2; rh++) {
            const int row = bm + wm*32 + mt*16 + g + rh*8;
#pragma unroll
            for (int nt = 0; nt < 8; nt++) {
                const int col = bn + wn*64 + nt*8 + 2*t4;
                *(float2*)(S + ((size_t)bh * Ln + row) * Ln + col) =
                    make_float2(acc[mt][nt][rh*2] * SCALEc, acc[mt][nt][rh*2+1] * SCALEc);
            }
        }
    }
}

// ================= AV: O = P @ V (r,i), cp.async + ldmatrix =================
#define LDSP 36
#define LDSV 36
__global__ __launch_bounds__(256, 2)
void av_mma(const float* __restrict__ S,
            const float* __restrict__ V_r, const float* __restrict__ V_i,
            float* __restrict__ Or, float* __restrict__ Oi)
{
    const int bh = blockIdx.z;
    const int bm = blockIdx.y * 128;
    const float* P = S + (size_t)bh * Ln * Ln;
    const size_t voff = (size_t)(bh >> 4) * Ln * Dn + (size_t)(bh & 15) * HDn;

    __shared__ float Ps[128*LDSP];
    __shared__ float Vtr[64*LDSV], Vti[64*LDSV];
    const uint32_t ps_b  = smem_u32(Ps);
    const uint32_t vtr_b = smem_u32(Vtr);
    const uint32_t vti_b = smem_u32(Vti);

    const int tid = threadIdx.x;
    const int wid = tid >> 5, lane = tid & 31;
    const int g = lane >> 2, t4 = lane & 3;
    const int wm = wid & 3, wn = wid >> 2;

    const int a_r = (lane & 7) + ((lane >> 3) & 1) * 8;
    const int a_c = (lane >> 4) * 4;
    const uint32_t a_off = (uint32_t)(((wm*32 + a_r) * LDSP + a_c) * 4);
    const int b_r = (lane & 7) + ((lane >> 4) ? 8 : 0);
    const int b_c = ((lane >> 3) & 1) * 4;
    const uint32_t b_off = (uint32_t)(((wn*32 + b_r) * LDSV + b_c) * 4);

    float accR[2][4][4], accI[2][4][4];
#pragma unroll
    for (int mt = 0; mt < 2; mt++)
#pragma unroll
        for (int nt = 0; nt < 4; nt++)
#pragma unroll
            for (int r = 0; r < 4; r++) { accR[mt][nt][r] = 0.f; accI[mt][nt][r] = 0.f; }

    const int kmax = bm + 128;
    for (int k0 = 0; k0 < kmax; k0 += 32) {
#pragma unroll
        for (int j = 0; j < 4; j++) {
            const int f = tid + j * 256;
            const int row = f >> 3, c4 = (f & 7) * 4;
            CP16(ps_b + (uint32_t)((row * LDSP + c4) * 4),
                 P + (size_t)(bm + row) * Ln + k0 + c4);
        }
        CP_COMMIT();
#pragma unroll
        for (int j = 0; j < 2; j++) {
            const int f = tid + j * 256;
            const int kr = f >> 4, c4 = (f & 15) * 4;
            const float4 vr = *(const float4*)(V_r + voff + (size_t)(k0 + kr) * Dn + c4);
            const float4 vi = *(const float4*)(V_i + voff + (size_t)(k0 + kr) * Dn + c4);
            Vtr[(c4+0)*LDSV + kr] = rnaf(vr.x);
            Vtr[(c4+1)*LDSV + kr] = rnaf(vr.y);
            Vtr[(c4+2)*LDSV + kr] = rnaf(vr.z);
            Vtr[(c4+3)*LDSV + kr] = rnaf(vr.w);
            Vti[(c4+0)*LDSV + kr] = rnaf(vi.x);
            Vti[(c4+1)*LDSV + kr] = rnaf(vi.y);
            Vti[(c4+2)*LDSV + kr] = rnaf(vi.z);
            Vti[(c4+3)*LDSV + kr] = rnaf(vi.w);
        }
        CP_WAIT0();
        __syncthreads();
#pragma unroll
        for (int ks = 0; ks < 4; ks++) {
            const uint32_t ko = (uint32_t)(ks * 32);
            uint32_t af[2][4];
#pragma unroll
            for (int mt = 0; mt < 2; mt++)
                LDSM4(af[mt], ps_b + a_off + (uint32_t)(mt * 16 * LDSP * 4) + ko);
            uint32_t bvr[4][2], bvi[4][2];
#pragma unroll
            for (int ntp = 0; ntp < 2; ntp++) {
                const uint32_t bo = b_off + (uint32_t)(ntp * 16 * LDSV * 4) + ko;
                uint32_t t[4];
                LDSM4(t, vtr_b + bo);
                bvr[2*ntp][0]=t[0]; bvr[2*ntp][1]=t[1]; bvr[2*ntp+1][0]=t[2]; bvr[2*ntp+1][1]=t[3];
                LDSM4(t, vti_b + bo);
                bvi[2*ntp][0]=t[0]; bvi[2*ntp][1]=t[1]; bvi[2*ntp+1][0]=t[2]; bvi[2*ntp+1][1]=t[3];
            }
#pragma unroll
            for (int mt = 0; mt < 2; mt++)
#pragma unroll
                for (int nt = 0; nt < 4; nt++) {
                    MMA_TF32(accR[mt][nt], af[mt], bvr[nt]);
                    MMA_TF32(accI[mt][nt], af[mt], bvi[nt]);
                }
        }
        __syncthreads();
    }

#pragma unroll
    for (int mt = 0; mt < 2; mt++) {
#pragma unroll
        for (int rh = 0; rh < 2; rh++) {
            const int row = bm + wm*32 + mt*16 + g + rh*8;
#pragma unroll
            for (int nt = 0; nt < 4; nt++) {
                const int col = wn*32 + nt*8 + 2*t4;
                const size_t o0 = voff + (size_t)row*Dn + col;
                *(float2*)(Or + o0) = make_float2(rnaf(accR[mt][nt][rh*2]), rnaf(accR[mt][nt][rh*2+1]));
                *(float2*)(Oi + o0) = make_float2(rnaf(accI[mt][nt][rh*2]), rnaf(accI[mt][nt][rh*2+1]));
            }
        }
    }
}

// ---------------- complex layernorm (rounded outputs) -----------------------
__global__ void cln_kernel(const float* __restrict__ xr, const float* __restrict__ xi,
                           const float* __restrict__ gr, const float* __restrict__ gi,
                           const float* __restrict__ bre, const float* __restrict__ bim,
                           float* __restrict__ outr, float* __restrict__ outi)
{
    int row = blockIdx.x;
    const float* pr = xr + (size_t)row * Dn;
    const float* pi = xi + (size_t)row * Dn;
    __shared__ float s1[256], s2[256];
    int tid = threadIdx.x;
    float sr = 0.f, si = 0.f;
    for (int j = tid; j < Dn; j += 256) { sr += pr[j]; si += pi[j]; }
    s1[tid] = sr; s2[tid] = si;
    __syncthreads();
    for (int o = 128; o > 0; o >>= 1) {
        if (tid < o) { s1[tid] += s1[tid+o]; s2[tid] += s2[tid+o]; }
        __syncthreads();
    }
    float mr = s1[0] * (1.f/Dn), mi = s2[0] * (1.f/Dn);
    __syncthreads();
    float v = 0.f;
    for (int j = tid; j < Dn; j += 256) {
        float cr = pr[j] - mr, ci = pi[j] - mi;
        v += cr*cr + ci*ci;
    }
    s1[tid] = v;
    __syncthreads();
    for (int o = 128; o > 0; o >>= 1) {
        if (tid < o) s1[tid] += s1[tid+o];
        __syncthreads();
    }
    float inv = rsqrtf(s1[0] * (1.f/Dn) + EPSc);
    for (int j = tid; j < Dn; j += 256) {
        float nr = (pr[j]-mr)*inv, ni = (pi[j]-mi)*inv;
        outr[(size_t)row*Dn + j] = rnaf(nr*gr[j] - ni*gi[j] + bre[j]);
        outi[(size_t)row*Dn + j] = rnaf(nr*gi[j] + ni*gr[j] + bim[j]);
    }
}

// ---------------- RoPE (in place, rounded outputs) --------------------------
__global__ void rope_kernel(float* __restrict__ xr, float* __restrict__ xi)
{
    int idx = blockIdx.x * blockDim.x + threadIdx.x;
    int j = idx & 31;
    int t = idx >> 5;
    int h = t & (Hn-1); t >>= 4;
    int l = t & (Ln-1);
    int b = t >> 10;
    size_t base = ((size_t)(b*Ln + l)) * Dn + h * HDn;
    double invf = exp(-((double)(2*j) / (double)HDn) * 9.210340371976184);
    double th = (double)l * invf;
    double sd, cd;
    sincos(th, &sd, &cd);
    float c = (float)cd, s = (float)sd;
    float a0 = xr[base+j], a1 = xr[base+j+32];
    xr[base+j]    = rnaf(a0*c - a1*s);
    xr[base+j+32] = rnaf(a1*c + a0*s);
    float b0 = xi[base+j], b1 = xi[base+j+32];
    xi[base+j]    = rnaf(b0*c - b1*s);
    xi[base+j+32] = rnaf(b1*c + b0*s);
}

// ---------------- causal softmax (rounded), zeroed up to tile edge ----------
__global__ void softmax_kernel(float* __restrict__ S)
{
    int row = blockIdx.x;
    int l = row & (Ln - 1);
    float* p = S + (size_t)row * Ln;
    __shared__ float red[256];
    int tid = threadIdx.x;
    float m = -1e30f;
    for (int j = tid; j <= l; j += 256) m = fmaxf(m, p[j]);
    red[tid] = m; __syncthreads();
    for (int o = 128; o > 0; o >>= 1) {
        if (tid < o) red[tid] = fmaxf(red[tid], red[tid+o]);
        __syncthreads();
    }
    m = red[0]; __syncthreads();
    float s = 0.f;
    for (int j = tid; j <= l; j += 256) s += expf(p[j] - m);
    red[tid] = s; __syncthreads();
    for (int o = 128; o > 0; o >>= 1) {
        if (tid < o) red[tid] += red[tid+o];
        __syncthreads();
    }
    float inv = 1.f / red[0];
    const int lim = (l & ~127) + 128;
    for (int j = tid; j < lim; j += 256)
        p[j] = (j <= l) ? rnaf(expf(p[j] - m) * inv) : 0.f;
}

// ---------------- ModReLU (rounded outputs) ---------------------------------
__global__ void modrelu_kernel(float* __restrict__ fr, float* __restrict__ fi,
                               const float* __restrict__ mb)
{
    size_t idx = (size_t)blockIdx.x * blockDim.x + threadIdx.x;
    int col = (int)(idx & (HIDn - 1));
    float r = fr[idx], i = fi[idx];
    float mag = sqrtf(r*r + i*i);
    float safe = mag > 0.f ? mag : 1.f;
    float act = fmaxf(mag + mb[col], 0.f);
    float fac = act / safe;
    fr[idx] = rnaf(r * fac);
    fi[idx] = rnaf(i * fac);
}

// ---------------- launch ----------------------------------------------------
extern "C" void kernel_launch(void* const* d_in, const int* in_sizes, int n_in,
                              void* d_out, int out_size)
{
    const float* x_r   = (const float*)d_in[0];
    const float* x_i   = (const float*)d_in[1];
    const float* Wq_r  = (const float*)d_in[2];
    const float* Wq_i  = (const float*)d_in[3];
    const float* Wk_r  = (const float*)d_in[4];
    const float* Wk_i  = (const float*)d_in[5];
    const float* Wv_r  = (const float*)d_in[6];
    const float* Wv_i  = (const float*)d_in[7];
    const float* Wo_r  = (const float*)d_in[8];
    const float* Wo_i  = (const float*)d_in[9];
    const float* bo_r  = (const float*)d_in[10];
    const float* bo_i  = (const float*)d_in[11];
    const float* ln1_gr = (const float*)d_in[12];
    const float* ln1_gi = (const float*)d_in[13];
    const float* ln1_br = (const float*)d_in[14];
    const float* ln1_bi = (const float*)d_in[15];
    const float* ln2_gr = (const float*)d_in[16];
    const float* ln2_gi = (const float*)d_in[17];
    const float* ln2_br = (const float*)d_in[18];
    const float* ln2_bi = (const float*)d_in[19];
    const float* W1_r  = (const float*)d_in[20];
    const float* W1_i  = (const float*)d_in[21];
    const float* b1_r  = (const float*)d_in[22];
    const float* b1_i  = (const float*)d_in[23];
    const float* W2_r  = (const float*)d_in[24];
    const float* W2_i  = (const float*)d_in[25];
    const float* b2_r  = (const float*)d_in[26];
    const float* b2_i  = (const float*)d_in[27];
    const float* mod_b = (const float*)d_in[28];
    float* out = (float*)d_out;

    float *hr, *hi, *qr, *qi, *kr, *ki, *vr, *vi, *sbuf, *aor, *aoi, *ar, *ai, *fr, *fi;
    cudaGetSymbolAddress((void**)&hr,  g_hr);
    cudaGetSymbolAddress((void**)&hi,  g_hi);
    cudaGetSymbolAddress((void**)&qr,  g_qr);
    cudaGetSymbolAddress((void**)&qi,  g_qi);
    cudaGetSymbolAddress((void**)&kr,  g_kr);
    cudaGetSymbolAddress((void**)&ki,  g_ki);
    cudaGetSymbolAddress((void**)&vr,  g_vr);
    cudaGetSymbolAddress((void**)&vi,  g_vi);
    cudaGetSymbolAddress((void**)&sbuf, g_s);
    cudaGetSymbolAddress((void**)&aor, g_aor);
    cudaGetSymbolAddress((void**)&aoi, g_aoi);
    cudaGetSymbolAddress((void**)&ar,  g_ar);
    cudaGetSymbolAddress((void**)&ai,  g_ai);
    cudaGetSymbolAddress((void**)&fr,  g_fr);
    cudaGetSymbolAddress((void**)&fi,  g_fi);

    cudaFuncSetAttribute(cmma_gemm,  cudaFuncAttributeMaxDynamicSharedMemorySize, SMEM_GEMM);
    cudaFuncSetAttribute(scores_mma, cudaFuncAttributeMaxDynamicSharedMemorySize, SMEM_SC);

    // 1. LN1 (rounded)
    cln_kernel<<<Mn, 256>>>(x_r, x_i, ln1_gr, ln1_gi, ln1_br, ln1_bi, hr, hi);

    // 2. QKV projections
    dim3 gproj(Dn/BNg, Mn/BMg);
    cmma_gemm<<<gproj, 256, SMEM_GEMM>>>(hr, hi, Wq_r, Wq_i, qr, qi, Mn, Dn, Dn, nullptr, nullptr, nullptr, nullptr);
    cmma_gemm<<<gproj, 256, SMEM_GEMM>>>(hr, hi, Wk_r, Wk_i, kr, ki, Mn, Dn, Dn, nullptr, nullptr, nullptr, nullptr);
    cmma_gemm<<<gproj, 256, SMEM_GEMM>>>(hr, hi, Wv_r, Wv_i, vr, vi, Mn, Dn, Dn, nullptr, nullptr, nullptr, nullptr);

    // 3. RoPE on Q and K (rounded)
    rope_kernel<<<(Bn*Ln*Hn*32)/256, 256>>>(qr, qi);
    rope_kernel<<<(Bn*Ln*Hn*32)/256, 256>>>(kr, ki);

    // 4. attention
    scores_mma<<<dim3(Ln/128, Ln/128, Bn*Hn), 256, SMEM_SC>>>(qr, qi, kr, ki, sbuf);
    softmax_kernel<<<Bn*Hn*Ln, 256>>>(sbuf);
    av_mma<<<dim3(1, Ln/128, Bn*Hn), 256>>>(sbuf, vr, vi, aor, aoi);

    // 5. out projection + bias + residual(x)
    cmma_gemm<<<gproj, 256, SMEM_GEMM>>>(aor, aoi, Wo_r, Wo_i, ar, ai, Mn, Dn, Dn, bo_r, bo_i, x_r, x_i);

    // 6. LN2 (rounded)
    cln_kernel<<<Mn, 256>>>(ar, ai, ln2_gr, ln2_gi, ln2_br, ln2_bi, hr, hi);

    // 7. FC1 + bias
    cmma_gemm<<<dim3(HIDn/BNg, Mn/BMg), 256, SMEM_GEMM>>>(hr, hi, W1_r, W1_i, fr, fi, Mn, HIDn, Dn, b1_r, b1_i, nullptr, nullptr);

    // 8. ModReLU (rounded)
    modrelu_kernel<<<(Mn*(size_t)HIDn)/256, 256>>>(fr, fi, mod_b);

    // 9. FC2 + bias + residual(ar/ai) -> output
    cmma_gemm<<<gproj, 256, SMEM_GEMM>>>(fr, fi, W2_r, W2_i, out, out + (size_t)Mn*Dn, Mn, Dn, HIDn, b2_r, b2_i, ar, ai);
}

// round 12
// speedup vs baseline: 1.9075x; 1.5876x over previous
#include <cuda_runtime.h>
#include <cuda_fp16.h>
#include <cstdint>
#include <math.h>

#define Bn   2
#define Ln   1024
#define Dn   1024
#define Hn   16
#define HDn  64
#define HIDn 4096
#define Mn   (Bn*Ln)        /* 2048 rows */
#define EPSc 1e-6f
#define SCALEc 0.125f       /* 64^-0.5 */

// ---------------- scratch (device globals; no runtime allocation) ----------
__device__ __half g_h16r[Mn*Dn],  g_h16i[Mn*Dn];
__device__ __half g_q16r[Mn*Dn],  g_q16i[Mn*Dn];
__device__ __half g_k16r[Mn*Dn],  g_k16i[Mn*Dn];
__device__ __half g_v16r[Mn*Dn],  g_v16i[Mn*Dn];
__device__ float  g_s [Bn*Hn*Ln*Ln];           /* 128 MB scores (fp32) */
__device__ __half g_p16[Bn*Hn*Ln*Ln];          /* 64 MB attn probs (fp16) */
__device__ __half g_ao16r[Mn*Dn], g_ao16i[Mn*Dn];
__device__ float  g_ar[Mn*Dn],  g_ai[Mn*Dn];
__device__ float  g_fr[Mn*HIDn], g_fi[Mn*HIDn];
__device__ __half g_f16r[Mn*HIDn], g_f16i[Mn*HIDn];
// half weight copies
__device__ __half g_wq16r[Dn*Dn],   g_wq16i[Dn*Dn];
__device__ __half g_wk16r[Dn*Dn],   g_wk16i[Dn*Dn];
__device__ __half g_wv16r[Dn*Dn],   g_wv16i[Dn*Dn];
__device__ __half g_wo16r[Dn*Dn],   g_wo16i[Dn*Dn];
__device__ __half g_w116r[HIDn*Dn], g_w116i[HIDn*Dn];
__device__ __half g_w216r[Dn*HIDn], g_w216i[Dn*HIDn];

// ================= helpers (baseline PTX only) ==============================
__device__ __forceinline__ uint32_t smem_u32(const void* p) {
    uint32_t a;
    asm("{ .reg .u64 t; cvta.to.shared.u64 t, %1; cvt.u32.u64 %0, t; }" : "=r"(a) : "l"(p));
    return a;
}
#define CP16(dst_u32, src_ptr) \
    asm volatile("cp.async.cg.shared.global [%0], [%1], 16;" :: "r"(dst_u32), "l"(src_ptr) : "memory")
#define CP_COMMIT() asm volatile("cp.async.commit_group;" ::: "memory")
#define CP_WAIT1()  asm volatile("cp.async.wait_group 1;" ::: "memory")
#define CP_WAIT0()  asm volatile("cp.async.wait_group 0;" ::: "memory")

#define MMA_F16(d, a, b) \
    asm volatile("mma.sync.aligned.m16n8k16.row.col.f32.f16.f16.f32 " \
        "{%0,%1,%2,%3}, {%4,%5,%6,%7}, {%8,%9}, {%0,%1,%2,%3};" \
        : "+f"((d)[0]), "+f"((d)[1]), "+f"((d)[2]), "+f"((d)[3]) \
        : "r"((a)[0]), "r"((a)[1]), "r"((a)[2]), "r"((a)[3]), \
          "r"((b)[0]), "r"((b)[1]))

#define LDSM4(r, addr) \
    asm volatile("ldmatrix.sync.aligned.m8n8.x4.shared.b16 {%0,%1,%2,%3}, [%4];" \
        : "=r"((r)[0]), "=r"((r)[1]), "=r"((r)[2]), "=r"((r)[3]) : "r"(addr))
#define LDSM4T(r, addr) \
    asm volatile("ldmatrix.sync.aligned.m8n8.x4.trans.shared.b16 {%0,%1,%2,%3}, [%4];" \
        : "=r"((r)[0]), "=r"((r)[1]), "=r"((r)[2]), "=r"((r)[3]) : "r"(addr))

// ================= weight prep: fp32 -> fp16 rn ==============================
__global__ void wprep16(const float4* __restrict__ wr, const float4* __restrict__ wi,
                        __half2* __restrict__ owr, __half2* __restrict__ owi, int n4)
{
    int i = blockIdx.x * 256 + threadIdx.x;
    if (i >= n4) return;
    float4 r = wr[i], m = wi[i];
    owr[2*i]   = __floats2half2_rn(r.x, r.y);
    owr[2*i+1] = __floats2half2_rn(r.z, r.w);
    owi[2*i]   = __floats2half2_rn(m.x, m.y);
    owi[2*i+1] = __floats2half2_rn(m.z, m.w);
}

// ================= complex GEMM fp16, cp.async + ldmatrix ===================
// C = A @ B^T (complex). A:[M,K], B:[N,K] half row-major.
// Block 128x64, BK=64 halves, 8 warps (4m x 2n), warp tile 32x32 (m16n8k16).
#define BMg 128
#define BNg 64
#define BKg 64
#define LDKh 72                       /* halves per row; 144B stride conflict-free */
#define A_TILE_B (BMg*LDKh*2)         /* 18432 */
#define B_TILE_B (BNg*LDKh*2)         /*  9216 */
#define OFF_AR 0
#define OFF_AI (A_TILE_B)
#define OFF_BR (2*A_TILE_B)
#define OFF_BI (2*A_TILE_B + B_TILE_B)
#define STG_BYTES (2*A_TILE_B + 2*B_TILE_B)   /* 55296 */
#define SMEM_GEMM (2*STG_BYTES)               /* 110592 */

__global__ __launch_bounds__(256, 2)
void hgemm(const __half* __restrict__ Ar, const __half* __restrict__ Ai,
           const __half* __restrict__ Br, const __half* __restrict__ Bi,
           float* __restrict__ Cr, float* __restrict__ Ci,
           __half* __restrict__ Crh, __half* __restrict__ Cih,
           int M, int N, int K,
           const float* __restrict__ biasr, const float* __restrict__ biasi,
           const float* __restrict__ resr,  const float* __restrict__ resi)
{
    extern __shared__ char smemc[];
    const uint32_t sb = smem_u32(smemc);
    const int tid = threadIdx.x;
    const int wid = tid >> 5, lane = tid & 31;
    const int g = lane >> 2, t4 = lane & 3;
    const int wm = wid & 3, wn = wid >> 2;
    const int bm = blockIdx.y * BMg, bn = blockIdx.x * BNg;
    const int row8 = tid >> 3, c8 = (tid & 7) * 8;          // 8-half chunks

    // ldmatrix per-lane byte offsets (fp16 fragments)
    const uint32_t a_base = (uint32_t)(((wm*32 + (lane & 15)) * LDKh + (lane >> 4) * 8) * 2);
    const uint32_t b_base = (uint32_t)(((wn*32 + (lane & 7) + ((lane >> 4) ? 8 : 0)) * LDKh
                                        + ((lane >> 3) & 1) * 8) * 2);

    float accR[2][4][4], accI[2][4][4];
#pragma unroll
    for (int mt = 0; mt < 2; mt++)
#pragma unroll
        for (int nt = 0; nt < 4; nt++)
#pragma unroll
            for (int r = 0; r < 4; r++) { accR[mt][nt][r] = 0.f; accI[mt][nt][r] = 0.f; }

    const int nch = K / BKg;
    auto prefetch = [&](int ch) {
        const uint32_t dst = sb + (uint32_t)((ch & 1) * STG_BYTES);
        const int k0 = ch * BKg;
#pragma unroll
        for (int j = 0; j < 4; j++) {
            const int row = row8 + j * 32;
            const uint32_t o = (uint32_t)((row * LDKh + c8) * 2);
            const size_t ga = (size_t)(bm + row) * K + k0 + c8;
            CP16(dst + OFF_AR + o, Ar + ga);
            CP16(dst + OFF_AI + o, Ai + ga);
        }
#pragma unroll
        for (int j = 0; j < 2; j++) {
            const int row = row8 + j * 32;
            const uint32_t o = (uint32_t)((row * LDKh + c8) * 2);
            const size_t gb = (size_t)(bn + row) * K + k0 + c8;
            CP16(dst + OFF_BR + o, Br + gb);
            CP16(dst + OFF_BI + o, Bi + gb);
        }
    };

    prefetch(0);
    CP_COMMIT();
    for (int ch = 0; ch < nch; ch++) {
        if (ch + 1 < nch) prefetch(ch + 1);
        CP_COMMIT();
        CP_WAIT1();
        __syncthreads();
        const uint32_t su = sb + (uint32_t)((ch & 1) * STG_BYTES);
#pragma unroll
        for (int ks = 0; ks < 4; ks++) {
            const uint32_t ko = (uint32_t)(ks * 32);        // 16 halves
            uint32_t afr[2][4], afi[2][4];
#pragma unroll
            for (int mt = 0; mt < 2; mt++) {
                const uint32_t ao = su + a_base + (uint32_t)(mt * 16 * LDKh * 2) + ko;
                LDSM4(afr[mt], ao + OFF_AR);
                LDSM4(afi[mt], ao + OFF_AI);
            }
            uint32_t br_[4][2], bi_[4][2];
#pragma unroll
            for (int ng = 0; ng < 2; ng++) {
                const uint32_t bo = su + b_base + (uint32_t)(ng * 16 * LDKh * 2) + ko;
                uint32_t t[4];
                LDSM4(t, bo + OFF_BR);
                br_[2*ng][0]=t[0]; br_[2*ng][1]=t[1]; br_[2*ng+1][0]=t[2]; br_[2*ng+1][1]=t[3];
                LDSM4(t, bo + OFF_BI);
                bi_[2*ng][0]=t[0]; bi_[2*ng][1]=t[1]; bi_[2*ng+1][0]=t[2]; bi_[2*ng+1][1]=t[3];
            }
#pragma unroll
            for (int mt = 0; mt < 2; mt++) {
                uint32_t afn[4];
#pragma unroll
                for (int r = 0; r < 4; r++) afn[r] = afi[mt][r] ^ 0x80008000u;
#pragma unroll
                for (int nt = 0; nt < 4; nt++) {
                    MMA_F16(accR[mt][nt], afr[mt], br_[nt]);
                    MMA_F16(accR[mt][nt], afn,     bi_[nt]);
                    MMA_F16(accI[mt][nt], afr[mt], bi_[nt]);
                    MMA_F16(accI[mt][nt], afi[mt], br_[nt]);
                }
            }
        }
        __syncthreads();
    }

#pragma unroll
    for (int mt = 0; mt < 2; mt++) {
#pragma unroll
        for (int rh = 0; rh < 2; rh++) {
            const int row = bm + wm*32 + mt*16 + g + rh*8;
#pragma unroll
            for (int nt = 0; nt < 4; nt++) {
                const int col = bn + wn*32 + nt*8 + 2*t4;
                float vr0 = accR[mt][nt][rh*2],   vr1 = accR[mt][nt][rh*2+1];
                float vi0 = accI[mt][nt][rh*2],   vi1 = accI[mt][nt][rh*2+1];
                if (Crh) {
                    *(__half2*)(Crh + (size_t)row*N + col) = __floats2half2_rn(vr0, vr1);
                    *(__half2*)(Cih + (size_t)row*N + col) = __floats2half2_rn(vi0, vi1);
                } else {
                    if (biasr) {
                        vr0 += biasr[col]; vr1 += biasr[col+1];
                        vi0 += biasi[col]; vi1 += biasi[col+1];
                    }
                    if (resr) {
                        const float2 rr = *(const float2*)(resr + (size_t)row*N + col);
                        const float2 ri = *(const float2*)(resi + (size_t)row*N + col);
                        vr0 += rr.x; vr1 += rr.y; vi0 += ri.x; vi1 += ri.y;
                    }
                    *(float2*)(Cr + (size_t)row*N + col) = make_float2(vr0, vr1);
                    *(float2*)(Ci + (size_t)row*N + col) = make_float2(vi0, vi1);
                }
            }
        }
    }
}

// ================= scores: S = (QrKr^T + QiKi^T)*SCALE, fp16 ===============
#define LDSQh 72
#define QT_B (128*LDSQh*2)    /* 18432 */
#define SMEM_SC (4*QT_B)      /* 73728 */

__global__ __launch_bounds__(256, 2)
void scores16(const __half* __restrict__ Q_r, const __half* __restrict__ Q_i,
              const __half* __restrict__ K_r, const __half* __restrict__ K_i,
              float* __restrict__ S)
{
    if (blockIdx.x > blockIdx.y) return;
    const int bh = blockIdx.z;
    const int bm = blockIdx.y * 128, bn = blockIdx.x * 128;
    const size_t off = (size_t)(bh >> 4) * Ln * Dn + (size_t)(bh & 15) * HDn;
    extern __shared__ char smemc[];
    const uint32_t sb = smem_u32(smemc);

    const int tid = threadIdx.x;
    const int wid = tid >> 5, lane = tid & 31;
    const int g = lane >> 2, t4 = lane & 3;
    const int wm = wid & 3, wn = wid >> 2;       // warp tile 32x64

#pragma unroll
    for (int j = 0; j < 4; j++) {
        const int f = tid + j * 256;             // 0..1023
        const int row = f >> 3, c8 = (f & 7) * 8;
        const uint32_t o = (uint32_t)((row * LDSQh + c8) * 2);
        const size_t gq = off + (size_t)(bm + row) * Dn + c8;
        const size_t gk = off + (size_t)(bn + row) * Dn + c8;
        CP16(sb + 0*QT_B + o, Q_r + gq);
        CP16(sb + 1*QT_B + o, Q_i + gq);
        CP16(sb + 2*QT_B + o, K_r + gk);
        CP16(sb + 3*QT_B + o, K_i + gk);
    }
    CP_COMMIT();
    CP_WAIT0();
    __syncthreads();

    const uint32_t a_base = (uint32_t)(((wm*32 + (lane & 15)) * LDSQh + (lane >> 4) * 8) * 2);
    const uint32_t b_base = (uint32_t)(((wn*64 + (lane & 7) + ((lane >> 4) ? 8 : 0)) * LDSQh
                                        + ((lane >> 3) & 1) * 8) * 2);

    float acc[2][8][4];
#pragma unroll
    for (int mt = 0; mt < 2; mt++)
#pragma unroll
        for (int nt = 0; nt < 8; nt++)
#pragma unroll
            for (int r = 0; r < 4; r++) acc[mt][nt][r] = 0.f;

#pragma unroll
    for (int ks = 0; ks < 4; ks++) {              // K = 64 halves
        const uint32_t ko = (uint32_t)(ks * 32);
        uint32_t aqr[2][4], aqi[2][4];
#pragma unroll
        for (int mt = 0; mt < 2; mt++) {
            const uint32_t ao = sb + a_base + (uint32_t)(mt * 16 * LDSQh * 2) + ko;
            LDSM4(aqr[mt], ao + 0*QT_B);
            LDSM4(aqi[mt], ao + 1*QT_B);
        }
        uint32_t bkr[8][2], bki[8][2];
#pragma unroll
        for (int ng = 0; ng < 4; ng++) {
            const uint32_t bo = sb + b_base + (uint32_t)(ng * 16 * LDSQh * 2) + ko;
            uint32_t t[4];
            LDSM4(t, bo + 2*QT_B);
            bkr[2*ng][0]=t[0]; bkr[2*ng][1]=t[1]; bkr[2*ng+1][0]=t[2]; bkr[2*ng+1][1]=t[3];
            LDSM4(t, bo + 3*QT_B);
            bki[2*ng][0]=t[0]; bki[2*ng][1]=t[1]; bki[2*ng+1][0]=t[2]; bki[2*ng+1][1]=t[3];
        }
#pragma unroll
        for (int mt = 0; mt < 2; mt++)
#pragma unroll
            for (int nt = 0; nt < 8; nt++) {
                MMA_F16(acc[mt][nt], aqr[mt], bkr[nt]);
                MMA_F16(acc[mt][nt], aqi[mt], bki[nt]);
            }
    }

#pragma unroll
    for (int mt = 0; mt < 2; mt++) {
#pragma unroll
        for (int rh = 0; rh < 2; rh++) {
            const int row = bm + wm*32 + mt*16 + g + rh*8;
#pragma unroll
            for (int nt = 0; nt < 8; nt++) {
                const int col = bn + wn*64 + nt*8 + 2*t4;
                *(float2*)(S + ((size_t)bh * Ln + row) * Ln + col) =
                    make_float2(acc[mt][nt][rh*2] * SCALEc, acc[mt][nt][rh*2+1] * SCALEc);
            }
        }
    }
}

// ================= AV: O = P @ V, fp16, fully cp.async ======================
#define LDSPh 72
#define LDSVh 72
__global__ __launch_bounds__(256, 2)
void av16(const __half* __restrict__ P16,
          const __half* __restrict__ V_r, const __half* __restrict__ V_i,
          __half* __restrict__ Or, __half* __restrict__ Oi)
{
    const int bh = blockIdx.z;
    const int bm = blockIdx.y * 128;
    const __half* P = P16 + (size_t)bh * Ln * Ln;
    const size_t voff = (size_t)(bh >> 4) * Ln * Dn + (size_t)(bh & 15) * HDn;

    __shared__ __half Ps[128*LDSPh];               /* 18432 B */
    __shared__ __half Vr_s[64*LDSVh], Vi_s[64*LDSVh];  /* [k][n], 9216 B each */
    const uint32_t ps_b = smem_u32(Ps);
    const uint32_t vr_b = smem_u32(Vr_s);
    const uint32_t vi_b = smem_u32(Vi_s);

    const int tid = threadIdx.x;
    const int wid = tid >> 5, lane = tid & 31;
    const int g = lane >> 2, t4 = lane & 3;
    const int wm = wid & 3, wn = wid >> 2;

    const uint32_t a_base = (uint32_t)(((wm*32 + (lane & 15)) * LDSPh + (lane >> 4) * 8) * 2);
    // trans-B: row dir = k, col dir = n
    const uint32_t bt_base = (uint32_t)((((lane & 7) + ((lane >> 3) & 1) * 8) * LDSVh
                                         + (lane >> 4) * 8) * 2);

    float accR[2][4][4], accI[2][4][4];
#pragma unroll
    for (int mt = 0; mt < 2; mt++)
#pragma unroll
        for (int nt = 0; nt < 4; nt++)
#pragma unroll
            for (int r = 0; r < 4; r++) { accR[mt][nt][r] = 0.f; accI[mt][nt][r] = 0.f; }

    const int kmax = bm + 128;
    for (int k0 = 0; k0 < kmax; k0 += 64) {
        // stage P 128x64 halves
#pragma unroll
        for (int j = 0; j < 4; j++) {
            const int f = tid + j * 256;
            const int row = f >> 3, c8 = (f & 7) * 8;
            CP16(ps_b + (uint32_t)((row * LDSPh + c8) * 2),
                 P + (size_t)(bm + row) * Ln + k0 + c8);
        }
        // stage V 64x64 halves [k][n] (consumed via ldmatrix.trans)
#pragma unroll
        for (int j = 0; j < 2; j++) {
            const int f = tid + j * 256;
            const int row = f >> 3, c8 = (f & 7) * 8;
            const uint32_t o = (uint32_t)((row * LDSVh + c8) * 2);
            const size_t gv = voff + (size_t)(k0 + row) * Dn + c8;
            CP16(vr_b + o, V_r + gv);
            CP16(vi_b + o, V_i + gv);
        }
        CP_COMMIT();
        CP_WAIT0();
        __syncthreads();
#pragma unroll
        for (int ks = 0; ks < 4; ks++) {
            const uint32_t ko_a = (uint32_t)(ks * 32);             // P: +16 halves in k
            const uint32_t ko_b = (uint32_t)(ks * 16 * LDSVh * 2); // V: +16 k-rows
            uint32_t af[2][4];
#pragma unroll
            for (int mt = 0; mt < 2; mt++)
                LDSM4(af[mt], ps_b + a_base + (uint32_t)(mt * 16 * LDSPh * 2) + ko_a);
            uint32_t bvr[4][2], bvi[4][2];
#pragma unroll
            for (int ng = 0; ng < 2; ng++) {
                const uint32_t bo = bt_base + ko_b + (uint32_t)((wn*32 + ng*16) * 2);
                uint32_t t[4];
                LDSM4T(t, vr_b + bo);
                bvr[2*ng][0]=t[0]; bvr[2*ng][1]=t[1]; bvr[2*ng+1][0]=t[2]; bvr[2*ng+1][1]=t[3];
                LDSM4T(t, vi_b + bo);
                bvi[2*ng][0]=t[0]; bvi[2*ng][1]=t[1]; bvi[2*ng+1][0]=t[2]; bvi[2*ng+1][1]=t[3];
            }
#pragma unroll
            for (int mt = 0; mt < 2; mt++)
#pragma unroll
                for (int nt = 0; nt < 4; nt++) {
                    MMA_F16(accR[mt][nt], af[mt], bvr[nt]);
                    MMA_F16(accI[mt][nt], af[mt], bvi[nt]);
                }
        }
        __syncthreads();
    }

#pragma unroll
    for (int mt = 0; mt < 2; mt++) {
#pragma unroll
        for (int rh = 0; rh < 2; rh++) {
            const int row = bm + wm*32 + mt*16 + g + rh*8;
#pragma unroll
            for (int nt = 0; nt < 4; nt++) {
                const int col = wn*32 + nt*8 + 2*t4;
                const size_t o0 = voff + (size_t)row*Dn + col;
                *(__half2*)(Or + o0) = __floats2half2_rn(accR[mt][nt][rh*2], accR[mt][nt][rh*2+1]);
                *(__half2*)(Oi + o0) = __floats2half2_rn(accI[mt][nt][rh*2], accI[mt][nt][rh*2+1]);
            }
        }
    }
}

// ---------------- complex layernorm (fp32 in, half out) ---------------------
__global__ void cln16(const float* __restrict__ xr, const float* __restrict__ xi,
                      const float* __restrict__ gr, const float* __restrict__ gi,
                      const float* __restrict__ bre, const float* __restrict__ bim,
                      __half* __restrict__ outr, __half* __restrict__ outi)
{
    int row = blockIdx.x;
    const float* pr = xr + (size_t)row * Dn;
    const float* pi = xi + (size_t)row * Dn;
    __shared__ float s1[256], s2[256];
    int tid = threadIdx.x;
    float sr = 0.f, si = 0.f;
    for (int j = tid; j < Dn; j += 256) { sr += pr[j]; si += pi[j]; }
    s1[tid] = sr; s2[tid] = si;
    __syncthreads();
    for (int o = 128; o > 0; o >>= 1) {
        if (tid < o) { s1[tid] += s1[tid+o]; s2[tid] += s2[tid+o]; }
        __syncthreads();
    }
    float mr = s1[0] * (1.f/Dn), mi = s2[0] * (1.f/Dn);
    __syncthreads();
    float v = 0.f;
    for (int j = tid; j < Dn; j += 256) {
        float cr = pr[j] - mr, ci = pi[j] - mi;
        v += cr*cr + ci*ci;
    }
    s1[tid] = v;
    __syncthreads();
    for (int o = 128; o > 0; o >>= 1) {
        if (tid < o) s1[tid] += s1[tid+o];
        __syncthreads();
    }
    float inv = rsqrtf(s1[0] * (1.f/Dn) + EPSc);
    for (int j = tid; j < Dn; j += 256) {
        float nr = (pr[j]-mr)*inv, ni = (pi[j]-mi)*inv;
        outr[(size_t)row*Dn + j] = __float2half_rn(nr*gr[j] - ni*gi[j] + bre[j]);
        outi[(size_t)row*Dn + j] = __float2half_rn(nr*gi[j] + ni*gr[j] + bim[j]);
    }
}

// ---------------- RoPE (in place on half arrays) ----------------------------
__global__ void rope16(__half* __restrict__ xr, __half* __restrict__ xi)
{
    int idx = blockIdx.x * blockDim.x + threadIdx.x;
    int j = idx & 31;
    int t = idx >> 5;
    int h = t & (Hn-1); t >>= 4;
    int l = t & (Ln-1);
    int b = t >> 10;
    size_t base = ((size_t)(b*Ln + l)) * Dn + h * HDn;
    double invf = exp(-((double)(2*j) / (double)HDn) * 9.210340371976184);
    double th = (double)l * invf;
    double sd, cd;
    sincos(th, &sd, &cd);
    float c = (float)cd, s = (float)sd;
    float a0 = __half2float(xr[base+j]), a1 = __half2float(xr[base+j+32]);
    xr[base+j]    = __float2half_rn(a0*c - a1*s);
    xr[base+j+32] = __float2half_rn(a1*c + a0*s);
    float b0 = __half2float(xi[base+j]), b1 = __half2float(xi[base+j+32]);
    xi[base+j]    = __float2half_rn(b0*c - b1*s);
    xi[base+j+32] = __float2half_rn(b1*c + b0*s);
}

// ---------------- causal softmax (fp32 in, half out) ------------------------
__global__ void softmax16(const float* __restrict__ S, __half* __restrict__ P16)
{
    int row = blockIdx.x;
    int l = row & (Ln - 1);
    const float* p = S + (size_t)row * Ln;
    __half* q = P16 + (size_t)row * Ln;
    __shared__ float red[256];
    int tid = threadIdx.x;
    float m = -1e30f;
    for (int j = tid; j <= l; j += 256) m = fmaxf(m, p[j]);
    red[tid] = m; __syncthreads();
    for (int o = 128; o > 0; o >>= 1) {
        if (tid < o) red[tid] = fmaxf(red[tid], red[tid+o]);
        __syncthreads();
    }
    m = red[0]; __syncthreads();
    float s = 0.f;
    for (int j = tid; j <= l; j += 256) s += expf(p[j] - m);
    red[tid] = s; __syncthreads();
    for (int o = 128; o > 0; o >>= 1) {
        if (tid < o) red[tid] += red[tid+o];
        __syncthreads();
    }
    float inv = 1.f / red[0];
    const int lim = (l & ~127) + 128;         // av only reads cols < lim
    for (int j = tid; j < lim; j += 256)
        q[j] = (j <= l) ? __float2half_rn(expf(p[j] - m) * inv) : __float2half_rn(0.f);
}

// ---------------- ModReLU (fp32 in, half out) -------------------------------
__global__ void modrelu16(const float* __restrict__ fr, const float* __restrict__ fi,
                          __half* __restrict__ gr, __half* __restrict__ gi,
                          const float* __restrict__ mb)
{
    size_t idx = (size_t)blockIdx.x * blockDim.x + threadIdx.x;
    int col = (int)(idx & (HIDn - 1));
    float r = fr[idx], i = fi[idx];
    float mag = sqrtf(r*r + i*i);
    float safe = mag > 0.f ? mag : 1.f;
    float act = fmaxf(mag + mb[col], 0.f);
    float fac = act / safe;
    gr[idx] = __float2half_rn(r * fac);
    gi[idx] = __float2half_rn(i * fac);
}

// ---------------- launch ----------------------------------------------------
extern "C" void kernel_launch(void* const* d_in, const int* in_sizes, int n_in,
                              void* d_out, int out_size)
{
    const float* x_r   = (const float*)d_in[0];
    const float* x_i   = (const float*)d_in[1];
    const float* Wq_r  = (const float*)d_in[2];
    const float* Wq_i  = (const float*)d_in[3];
    const float* Wk_r  = (const float*)d_in[4];
    const float* Wk_i  = (const float*)d_in[5];
    const float* Wv_r  = (const float*)d_in[6];
    const float* Wv_i  = (const float*)d_in[7];
    const float* Wo_r  = (const float*)d_in[8];
    const float* Wo_i  = (const float*)d_in[9];
    const float* bo_r  = (const float*)d_in[10];
    const float* bo_i  = (const float*)d_in[11];
    const float* ln1_gr = (const float*)d_in[12];
    const float* ln1_gi = (const float*)d_in[13];
    const float* ln1_br = (const float*)d_in[14];
    const float* ln1_bi = (const float*)d_in[15];
    const float* ln2_gr = (const float*)d_in[16];
    const float* ln2_gi = (const float*)d_in[17];
    const float* ln2_br = (const float*)d_in[18];
    const float* ln2_bi = (const float*)d_in[19];
    const float* W1_r  = (const float*)d_in[20];
    const float* W1_i  = (const float*)d_in[21];
    const float* b1_r  = (const float*)d_in[22];
    const float* b1_i  = (const float*)d_in[23];
    const float* W2_r  = (const float*)d_in[24];
    const float* W2_i  = (const float*)d_in[25];
    const float* b2_r  = (const float*)d_in[26];
    const float* b2_i  = (const float*)d_in[27];
    const float* mod_b = (const float*)d_in[28];
    float* out = (float*)d_out;

    __half *h16r, *h16i, *q16r, *q16i, *k16r, *k16i, *v16r, *v16i;
    __half *p16, *ao16r, *ao16i, *f16r, *f16i;
    __half *wq16r, *wq16i, *wk16r, *wk16i, *wv16r, *wv16i, *wo16r, *wo16i;
    __half *w116r, *w116i, *w216r, *w216i;
    float *sbuf, *ar, *ai, *fr, *fi;
    cudaGetSymbolAddress((void**)&h16r, g_h16r);  cudaGetSymbolAddress((void**)&h16i, g_h16i);
    cudaGetSymbolAddress((void**)&q16r, g_q16r);  cudaGetSymbolAddress((void**)&q16i, g_q16i);
    cudaGetSymbolAddress((void**)&k16r, g_k16r);  cudaGetSymbolAddress((void**)&k16i, g_k16i);
    cudaGetSymbolAddress((void**)&v16r, g_v16r);  cudaGetSymbolAddress((void**)&v16i, g_v16i);
    cudaGetSymbolAddress((void**)&sbuf, g_s);     cudaGetSymbolAddress((void**)&p16,  g_p16);
    cudaGetSymbolAddress((void**)&ao16r, g_ao16r);cudaGetSymbolAddress((void**)&ao16i, g_ao16i);
    cudaGetSymbolAddress((void**)&ar, g_ar);      cudaGetSymbolAddress((void**)&ai, g_ai);
    cudaGetSymbolAddress((void**)&fr, g_fr);      cudaGetSymbolAddress((void**)&fi, g_fi);
    cudaGetSymbolAddress((void**)&f16r, g_f16r);  cudaGetSymbolAddress((void**)&f16i, g_f16i);
    cudaGetSymbolAddress((void**)&wq16r, g_wq16r);cudaGetSymbolAddress((void**)&wq16i, g_wq16i);
    cudaGetSymbolAddress((void**)&wk16r, g_wk16r);cudaGetSymbolAddress((void**)&wk16i, g_wk16i);
    cudaGetSymbolAddress((void**)&wv16r, g_wv16r);cudaGetSymbolAddress((void**)&wv16i, g_wv16i);
    cudaGetSymbolAddress((void**)&wo16r, g_wo16r);cudaGetSymbolAddress((void**)&wo16i, g_wo16i);
    cudaGetSymbolAddress((void**)&w116r, g_w116r);cudaGetSymbolAddress((void**)&w116i, g_w116i);
    cudaGetSymbolAddress((void**)&w216r, g_w216r);cudaGetSymbolAddress((void**)&w216i, g_w216i);

    cudaFuncSetAttribute(hgemm,    cudaFuncAttributeMaxDynamicSharedMemorySize, SMEM_GEMM);
    cudaFuncSetAttribute(scores16, cudaFuncAttributeMaxDynamicSharedMemorySize, SMEM_SC);

    // 0. weight conversion to fp16
    const int n4d = Dn*Dn/4, n4h = HIDn*Dn/4;
    wprep16<<<n4d/256, 256>>>((const float4*)Wq_r, (const float4*)Wq_i, (__half2*)wq16r, (__half2*)wq16i, n4d);
    wprep16<<<n4d/256, 256>>>((const float4*)Wk_r, (const float4*)Wk_i, (__half2*)wk16r, (__half2*)wk16i, n4d);
    wprep16<<<n4d/256, 256>>>((const float4*)Wv_r, (const float4*)Wv_i, (__half2*)wv16r, (__half2*)wv16i, n4d);
    wprep16<<<n4d/256, 256>>>((const float4*)Wo_r, (const float4*)Wo_i, (__half2*)wo16r, (__half2*)wo16i, n4d);
    wprep16<<<n4h/256, 256>>>((const float4*)W1_r, (const float4*)W1_i, (__half2*)w116r, (__half2*)w116i, n4h);
    wprep16<<<n4h/256, 256>>>((const float4*)W2_r, (const float4*)W2_i, (__half2*)w216r, (__half2*)w216i, n4h);

    // 1. LN1 -> half
    cln16<<<Mn, 256>>>(x_r, x_i, ln1_gr, ln1_gi, ln1_br, ln1_bi, h16r, h16i);

    // 2. QKV projections (half in, half out)
    dim3 gproj(Dn/BNg, Mn/BMg);
    hgemm<<<gproj, 256, SMEM_GEMM>>>(h16r, h16i, wq16r, wq16i, nullptr, nullptr, q16r, q16i, Mn, Dn, Dn, nullptr, nullptr, nullptr, nullptr);
    hgemm<<<gproj, 256, SMEM_GEMM>>>(h16r, h16i, wk16r, wk16i, nullptr, nullptr, k16r, k16i, Mn, Dn, Dn, nullptr, nullptr, nullptr, nullptr);
    hgemm<<<gproj, 256, SMEM_GEMM>>>(h16r, h16i, wv16r, wv16i, nullptr, nullptr, v16r, v16i, Mn, Dn, Dn, nullptr, nullptr, nullptr, nullptr);

    // 3. RoPE on Q and K (half in place)
    rope16<<<(Bn*Ln*Hn*32)/256, 256>>>(q16r, q16i);
    rope16<<<(Bn*Ln*Hn*32)/256, 256>>>(k16r, k16i);

    // 4. attention
    scores16<<<dim3(Ln/128, Ln/128, Bn*Hn), 256, SMEM_SC>>>(q16r, q16i, k16r, k16i, sbuf);
    softmax16<<<Bn*Hn*Ln, 256>>>(sbuf, p16);
    av16<<<dim3(1, Ln/128, Bn*Hn), 256>>>(p16, v16r, v16i, ao16r, ao16i);

    // 5. out projection + bias + residual(x) -> fp32
    hgemm<<<gproj, 256, SMEM_GEMM>>>(ao16r, ao16i, wo16r, wo16i, ar, ai, nullptr, nullptr, Mn, Dn, Dn, bo_r, bo_i, x_r, x_i);

    // 6. LN2 -> half
    cln16<<<Mn, 256>>>(ar, ai, ln2_gr, ln2_gi, ln2_br, ln2_bi, h16r, h16i);

    // 7. FC1 + bias -> fp32
    hgemm<<<dim3(HIDn/BNg, Mn/BMg), 256, SMEM_GEMM>>>(h16r, h16i, w116r, w116i, fr, fi, nullptr, nullptr, Mn, HIDn, Dn, b1_r, b1_i, nullptr, nullptr);

    // 8. ModReLU -> half
    modrelu16<<<(Mn*(size_t)HIDn)/256, 256>>>(fr, fi, f16r, f16i, mod_b);

    // 9. FC2 + bias + residual(ar/ai) -> output (fp32)
    hgemm<<<gproj, 256, SMEM_GEMM>>>(f16r, f16i, w216r, w216i, out, out + (size_t)Mn*Dn, nullptr, nullptr, Mn, Dn, HIDn, b2_r, b2_i, ar, ai);
}

// round 14
// speedup vs baseline: 2.0786x; 1.0897x over previous
#include <cuda_runtime.h>
#include <cuda_fp16.h>
#include <cstdint>
#include <math.h>

#define Bn   2
#define Ln   1024
#define Dn   1024
#define Hn   16
#define HDn  64
#define HIDn 4096
#define Mn   (Bn*Ln)        /* 2048 rows */
#define EPSc 1e-6f
#define SCALEc 0.125f       /* 64^-0.5 */

// ---------------- scratch (device globals; no runtime allocation) ----------
__device__ __half g_h16r[Mn*Dn],  g_h16i[Mn*Dn];
__device__ __half g_q16r[Mn*Dn],  g_q16i[Mn*Dn];
__device__ __half g_k16r[Mn*Dn],  g_k16i[Mn*Dn];
__device__ __half g_v16r[Mn*Dn],  g_v16i[Mn*Dn];
__device__ __half g_ao16r[Mn*Dn], g_ao16i[Mn*Dn];
__device__ float  g_ar[Mn*Dn],  g_ai[Mn*Dn];
__device__ float  g_fr[Mn*HIDn], g_fi[Mn*HIDn];
__device__ __half g_f16r[Mn*HIDn], g_f16i[Mn*HIDn];
// half weight copies
__device__ __half g_wq16r[Dn*Dn],   g_wq16i[Dn*Dn];
__device__ __half g_wk16r[Dn*Dn],   g_wk16i[Dn*Dn];
__device__ __half g_wv16r[Dn*Dn],   g_wv16i[Dn*Dn];
__device__ __half g_wo16r[Dn*Dn],   g_wo16i[Dn*Dn];
__device__ __half g_w116r[HIDn*Dn], g_w116i[HIDn*Dn];
__device__ __half g_w216r[Dn*HIDn], g_w216i[Dn*HIDn];

// ================= helpers (baseline PTX only) ==============================
__device__ __forceinline__ uint32_t smem_u32(const void* p) {
    uint32_t a;
    asm("{ .reg .u64 t; cvta.to.shared.u64 t, %1; cvt.u32.u64 %0, t; }" : "=r"(a) : "l"(p));
    return a;
}
#define CP16(dst_u32, src_ptr) \
    asm volatile("cp.async.cg.shared.global [%0], [%1], 16;" :: "r"(dst_u32), "l"(src_ptr) : "memory")
#define CP_COMMIT() asm volatile("cp.async.commit_group;" ::: "memory")
#define CP_WAIT1()  asm volatile("cp.async.wait_group 1;" ::: "memory")
#define CP_WAIT0()  asm volatile("cp.async.wait_group 0;" ::: "memory")

#define MMA_F16(d, a, b) \
    asm volatile("mma.sync.aligned.m16n8k16.row.col.f32.f16.f16.f32 " \
        "{%0,%1,%2,%3}, {%4,%5,%6,%7}, {%8,%9}, {%0,%1,%2,%3};" \
        : "+f"((d)[0]), "+f"((d)[1]), "+f"((d)[2]), "+f"((d)[3]) \
        : "r"((a)[0]), "r"((a)[1]), "r"((a)[2]), "r"((a)[3]), \
          "r"((b)[0]), "r"((b)[1]))

#define LDSM4(r, addr) \
    asm volatile("ldmatrix.sync.aligned.m8n8.x4.shared.b16 {%0,%1,%2,%3}, [%4];" \
        : "=r"((r)[0]), "=r"((r)[1]), "=r"((r)[2]), "=r"((r)[3]) : "r"(addr))
#define LDSM4T(r, addr) \
    asm volatile("ldmatrix.sync.aligned.m8n8.x4.trans.shared.b16 {%0,%1,%2,%3}, [%4];" \
        : "=r"((r)[0]), "=r"((r)[1]), "=r"((r)[2]), "=r"((r)[3]) : "r"(addr))

__device__ __forceinline__ uint32_t packh2(float lo, float hi) {
    __half2 h = __floats2half2_rn(lo, hi);
    return *reinterpret_cast<uint32_t*>(&h);
}

// ================= weight prep: fp32 -> fp16 rn ==============================
__global__ void wprep16(const float4* __restrict__ wr, const float4* __restrict__ wi,
                        __half2* __restrict__ owr, __half2* __restrict__ owi, int n4)
{
    int i = blockIdx.x * 256 + threadIdx.x;
    if (i >= n4) return;
    float4 r = wr[i], m = wi[i];
    owr[2*i]   = __floats2half2_rn(r.x, r.y);
    owr[2*i+1] = __floats2half2_rn(r.z, r.w);
    owi[2*i]   = __floats2half2_rn(m.x, m.y);
    owi[2*i+1] = __floats2half2_rn(m.z, m.w);
}

// ================= complex GEMM fp16 (unchanged winner from R11) ============
#define BMg 128
#define BNg 64
#define BKg 64
#define LDKh 72
#define A_TILE_B (BMg*LDKh*2)
#define B_TILE_B (BNg*LDKh*2)
#define OFF_AR 0
#define OFF_AI (A_TILE_B)
#define OFF_BR (2*A_TILE_B)
#define OFF_BI (2*A_TILE_B + B_TILE_B)
#define STG_BYTES (2*A_TILE_B + 2*B_TILE_B)
#define SMEM_GEMM (2*STG_BYTES)

__global__ __launch_bounds__(256, 2)
void hgemm(const __half* __restrict__ Ar, const __half* __restrict__ Ai,
           const __half* __restrict__ Br, const __half* __restrict__ Bi,
           float* __restrict__ Cr, float* __restrict__ Ci,
           __half* __restrict__ Crh, __half* __restrict__ Cih,
           int M, int N, int K,
           const float* __restrict__ biasr, const float* __restrict__ biasi,
           const float* __restrict__ resr,  const float* __restrict__ resi)
{
    extern __shared__ char smemc[];
    const uint32_t sb = smem_u32(smemc);
    const int tid = threadIdx.x;
    const int wid = tid >> 5, lane = tid & 31;
    const int g = lane >> 2, t4 = lane & 3;
    const int wm = wid & 3, wn = wid >> 2;
    const int bm = blockIdx.y * BMg, bn = blockIdx.x * BNg;
    const int row8 = tid >> 3, c8 = (tid & 7) * 8;

    const uint32_t a_base = (uint32_t)(((wm*32 + (lane & 15)) * LDKh + (lane >> 4) * 8) * 2);
    const uint32_t b_base = (uint32_t)(((wn*32 + (lane & 7) + ((lane >> 4) ? 8 : 0)) * LDKh
                                        + ((lane >> 3) & 1) * 8) * 2);

    float accR[2][4][4], accI[2][4][4];
#pragma unroll
    for (int mt = 0; mt < 2; mt++)
#pragma unroll
        for (int nt = 0; nt < 4; nt++)
#pragma unroll
            for (int r = 0; r < 4; r++) { accR[mt][nt][r] = 0.f; accI[mt][nt][r] = 0.f; }

    const int nch = K / BKg;
    auto prefetch = [&](int ch) {
        const uint32_t dst = sb + (uint32_t)((ch & 1) * STG_BYTES);
        const int k0 = ch * BKg;
#pragma unroll
        for (int j = 0; j < 4; j++) {
            const int row = row8 + j * 32;
            const uint32_t o = (uint32_t)((row * LDKh + c8) * 2);
            const size_t ga = (size_t)(bm + row) * K + k0 + c8;
            CP16(dst + OFF_AR + o, Ar + ga);
            CP16(dst + OFF_AI + o, Ai + ga);
        }
#pragma unroll
        for (int j = 0; j < 2; j++) {
            const int row = row8 + j * 32;
            const uint32_t o = (uint32_t)((row * LDKh + c8) * 2);
            const size_t gb = (size_t)(bn + row) * K + k0 + c8;
            CP16(dst + OFF_BR + o, Br + gb);
            CP16(dst + OFF_BI + o, Bi + gb);
        }
    };

    prefetch(0);
    CP_COMMIT();
    for (int ch = 0; ch < nch; ch++) {
        if (ch + 1 < nch) prefetch(ch + 1);
        CP_COMMIT();
        CP_WAIT1();
        __syncthreads();
        const uint32_t su = sb + (uint32_t)((ch & 1) * STG_BYTES);
#pragma unroll
        for (int ks = 0; ks < 4; ks++) {
            const uint32_t ko = (uint32_t)(ks * 32);
            uint32_t afr[2][4], afi[2][4];
#pragma unroll
            for (int mt = 0; mt < 2; mt++) {
                const uint32_t ao = su + a_base + (uint32_t)(mt * 16 * LDKh * 2) + ko;
                LDSM4(afr[mt], ao + OFF_AR);
                LDSM4(afi[mt], ao + OFF_AI);
            }
            uint32_t br_[4][2], bi_[4][2];
#pragma unroll
            for (int ng = 0; ng < 2; ng++) {
                const uint32_t bo = su + b_base + (uint32_t)(ng * 16 * LDKh * 2) + ko;
                uint32_t t[4];
                LDSM4(t, bo + OFF_BR);
                br_[2*ng][0]=t[0]; br_[2*ng][1]=t[1]; br_[2*ng+1][0]=t[2]; br_[2*ng+1][1]=t[3];
                LDSM4(t, bo + OFF_BI);
                bi_[2*ng][0]=t[0]; bi_[2*ng][1]=t[1]; bi_[2*ng+1][0]=t[2]; bi_[2*ng+1][1]=t[3];
            }
#pragma unroll
            for (int mt = 0; mt < 2; mt++) {
                uint32_t afn[4];
#pragma unroll
                for (int r = 0; r < 4; r++) afn[r] = afi[mt][r] ^ 0x80008000u;
#pragma unroll
                for (int nt = 0; nt < 4; nt++) {
                    MMA_F16(accR[mt][nt], afr[mt], br_[nt]);
                    MMA_F16(accR[mt][nt], afn,     bi_[nt]);
                    MMA_F16(accI[mt][nt], afr[mt], bi_[nt]);
                    MMA_F16(accI[mt][nt], afi[mt], br_[nt]);
                }
            }
        }
        __syncthreads();
    }

#pragma unroll
    for (int mt = 0; mt < 2; mt++) {
#pragma unroll
        for (int rh = 0; rh < 2; rh++) {
            const int row = bm + wm*32 + mt*16 + g + rh*8;
#pragma unroll
            for (int nt = 0; nt < 4; nt++) {
                const int col = bn + wn*32 + nt*8 + 2*t4;
                float vr0 = accR[mt][nt][rh*2],   vr1 = accR[mt][nt][rh*2+1];
                float vi0 = accI[mt][nt][rh*2],   vi1 = accI[mt][nt][rh*2+1];
                if (Crh) {
                    *(__half2*)(Crh + (size_t)row*N + col) = __floats2half2_rn(vr0, vr1);
                    *(__half2*)(Cih + (size_t)row*N + col) = __floats2half2_rn(vi0, vi1);
                } else {
                    if (biasr) {
                        vr0 += biasr[col]; vr1 += biasr[col+1];
                        vi0 += biasi[col]; vi1 += biasi[col+1];
                    }
                    if (resr) {
                        const float2 rr = *(const float2*)(resr + (size_t)row*N + col);
                        const float2 ri = *(const float2*)(resi + (size_t)row*N + col);
                        vr0 += rr.x; vr1 += rr.y; vi0 += ri.x; vi1 += ri.y;
                    }
                    *(float2*)(Cr + (size_t)row*N + col) = make_float2(vr0, vr1);
                    *(float2*)(Ci + (size_t)row*N + col) = make_float2(vi0, vi1);
                }
            }
        }
    }
}

// ================= fused flash attention (scores+softmax+AV) ================
// One CTA per (bh, 128-row Q tile). 8 warps x 16 rows. Causal; online softmax.
#define FLD 72
#define FQT_B (128*FLD*2)          /* 18432 per tile (128 rows x 72 halves) */
#define FKV_B (4*FQT_B)            /* Kr,Ki,Vr,Vi per stage = 73728 */
#define SMEM_FA (2*FQT_B + 2*FKV_B) /* 184320 */

__global__ __launch_bounds__(256, 1)
void flash16(const __half* __restrict__ Q_r, const __half* __restrict__ Q_i,
             const __half* __restrict__ K_r, const __half* __restrict__ K_i,
             const __half* __restrict__ V_r, const __half* __restrict__ V_i,
             __half* __restrict__ Or, __half* __restrict__ Oi)
{
    const int bh = blockIdx.y;
    const int tile = blockIdx.x;
    const int bm = tile * 128;
    const size_t off = (size_t)(bh >> 4) * Ln * Dn + (size_t)(bh & 15) * HDn;
    extern __shared__ char smemc[];
    const uint32_t sb = smem_u32(smemc);
    const uint32_t qb = sb;                         /* Qr @0, Qi @FQT_B */

    const int tid = threadIdx.x;
    const int wid = tid >> 5, lane = tid & 31;
    const int g = lane >> 2, t4 = lane & 3;
    const int row8 = tid >> 3, c8 = (tid & 7) * 8;  /* staging: c8 in 0..56 */

    // ---- stage Q (128 x 64 halves, r+i) and prefetch K/V block 0 ----------
#pragma unroll
    for (int j = 0; j < 4; j++) {
        const int row = row8 + j * 32;
        const uint32_t o = (uint32_t)((row * FLD + c8) * 2);
        const size_t gq = off + (size_t)(bm + row) * Dn + c8;
        CP16(qb + o,          Q_r + gq);
        CP16(qb + FQT_B + o,  Q_i + gq);
    }
    auto prefetch_kv = [&](int kt) {
        const uint32_t dst = sb + 2*FQT_B + (uint32_t)((kt & 1) * FKV_B);
#pragma unroll
        for (int j = 0; j < 4; j++) {
            const int row = row8 + j * 32;
            const uint32_t o = (uint32_t)((row * FLD + c8) * 2);
            const size_t gk = off + (size_t)(kt*128 + row) * Dn + c8;
            CP16(dst + o,           K_r + gk);
            CP16(dst + FQT_B + o,   K_i + gk);
            CP16(dst + 2*FQT_B + o, V_r + gk);
            CP16(dst + 3*FQT_B + o, V_i + gk);
        }
    };
    prefetch_kv(0);
    CP_COMMIT();
    CP_WAIT0();
    __syncthreads();

    // ---- preload Q fragments (kept in registers for all K blocks) ---------
    const uint32_t aq_base = (uint32_t)(((wid*16 + (lane & 15)) * FLD + (lane >> 4) * 8) * 2);
    uint32_t aqr[4][4], aqi[4][4];
#pragma unroll
    for (int ks = 0; ks < 4; ks++) {
        LDSM4(aqr[ks], qb + aq_base + (uint32_t)(ks * 32));
        LDSM4(aqi[ks], qb + FQT_B + aq_base + (uint32_t)(ks * 32));
    }

    // K B-frag base (rows = key index, full 128 covered via ng loop)
    const uint32_t bk_base = (uint32_t)((((lane & 7) + ((lane >> 4) ? 8 : 0)) * FLD
                                         + ((lane >> 3) & 1) * 8) * 2);
    // V trans-B base (rows = k, cols = n)
    const uint32_t bv_base = (uint32_t)((((lane & 7) + ((lane >> 3) & 1) * 8) * FLD
                                         + (lane >> 4) * 8) * 2);

    float oR[8][4], oI[8][4];
#pragma unroll
    for (int nt = 0; nt < 8; nt++)
#pragma unroll
        for (int r = 0; r < 4; r++) { oR[nt][r] = 0.f; oI[nt][r] = 0.f; }
    float m0 = -1e30f, m1 = -1e30f, s0 = 0.f, s1 = 0.f;

    const int row0 = bm + wid*16 + g;        /* rows this thread owns */
    const int row1 = row0 + 8;

    for (int kt = 0; kt <= tile; kt++) {
        if (kt < tile) { prefetch_kv(kt + 1); CP_COMMIT(); }
        const uint32_t kvb = sb + 2*FQT_B + (uint32_t)((kt & 1) * FKV_B);

        // ---- S = (QrKr^T + QiKi^T), 16x128 per warp -----------------------
        float sacc[16][4];
#pragma unroll
        for (int nt = 0; nt < 16; nt++)
#pragma unroll
            for (int r = 0; r < 4; r++) sacc[nt][r] = 0.f;
#pragma unroll
        for (int ks = 0; ks < 4; ks++) {
            const uint32_t ko = (uint32_t)(ks * 32);
#pragma unroll
            for (int ng = 0; ng < 8; ng++) {
                const uint32_t bo = kvb + bk_base + (uint32_t)(ng * 16 * FLD * 2) + ko;
                uint32_t tkr[4], tki[4];
                LDSM4(tkr, bo);
                LDSM4(tki, bo + FQT_B);
                uint32_t blo[2] = {tkr[0], tkr[1]}, bhi[2] = {tkr[2], tkr[3]};
                MMA_F16(sacc[2*ng],   aqr[ks], blo);
                MMA_F16(sacc[2*ng+1], aqr[ks], bhi);
                blo[0] = tki[0]; blo[1] = tki[1]; bhi[0] = tki[2]; bhi[1] = tki[3];
                MMA_F16(sacc[2*ng],   aqi[ks], blo);
                MMA_F16(sacc[2*ng+1], aqi[ks], bhi);
            }
        }
        // scale + causal mask (only diagonal block needs it)
        if (kt == tile) {
#pragma unroll
            for (int nt = 0; nt < 16; nt++) {
                const int c0 = kt*128 + nt*8 + 2*t4;
                sacc[nt][0] = (c0   <= row0) ? sacc[nt][0]*SCALEc : -1e30f;
                sacc[nt][1] = (c0+1 <= row0) ? sacc[nt][1]*SCALEc : -1e30f;
                sacc[nt][2] = (c0   <= row1) ? sacc[nt][2]*SCALEc : -1e30f;
                sacc[nt][3] = (c0+1 <= row1) ? sacc[nt][3]*SCALEc : -1e30f;
            }
        } else {
#pragma unroll
            for (int nt = 0; nt < 16; nt++)
#pragma unroll
                for (int r = 0; r < 4; r++) sacc[nt][r] *= SCALEc;
        }

        // ---- online softmax update ---------------------------------------
        float mx0 = -1e30f, mx1 = -1e30f;
#pragma unroll
        for (int nt = 0; nt < 16; nt++) {
            mx0 = fmaxf(mx0, fmaxf(sacc[nt][0], sacc[nt][1]));
            mx1 = fmaxf(mx1, fmaxf(sacc[nt][2], sacc[nt][3]));
        }
        mx0 = fmaxf(mx0, __shfl_xor_sync(0xffffffffu, mx0, 1));
        mx0 = fmaxf(mx0, __shfl_xor_sync(0xffffffffu, mx0, 2));
        mx1 = fmaxf(mx1, __shfl_xor_sync(0xffffffffu, mx1, 1));
        mx1 = fmaxf(mx1, __shfl_xor_sync(0xffffffffu, mx1, 2));
        const float nm0 = fmaxf(m0, mx0), nm1 = fmaxf(m1, mx1);
        const float f0 = expf(m0 - nm0), f1 = expf(m1 - nm1);
        float sum0 = 0.f, sum1 = 0.f;
#pragma unroll
        for (int nt = 0; nt < 16; nt++) {
            sacc[nt][0] = expf(sacc[nt][0] - nm0);
            sacc[nt][1] = expf(sacc[nt][1] - nm0);
            sacc[nt][2] = expf(sacc[nt][2] - nm1);
            sacc[nt][3] = expf(sacc[nt][3] - nm1);
            sum0 += sacc[nt][0] + sacc[nt][1];
            sum1 += sacc[nt][2] + sacc[nt][3];
        }
        sum0 += __shfl_xor_sync(0xffffffffu, sum0, 1);
        sum0 += __shfl_xor_sync(0xffffffffu, sum0, 2);
        sum1 += __shfl_xor_sync(0xffffffffu, sum1, 1);
        sum1 += __shfl_xor_sync(0xffffffffu, sum1, 2);
        s0 = s0 * f0 + sum0;
        s1 = s1 * f1 + sum1;
        m0 = nm0; m1 = nm1;
#pragma unroll
        for (int nt = 0; nt < 8; nt++) {
            oR[nt][0] *= f0; oR[nt][1] *= f0; oR[nt][2] *= f1; oR[nt][3] *= f1;
            oI[nt][0] *= f0; oI[nt][1] *= f0; oI[nt][2] *= f1; oI[nt][3] *= f1;
        }

        // ---- O += P @ V (P fragments built in registers) ------------------
#pragma unroll
        for (int kc = 0; kc < 8; kc++) {
            uint32_t pa[4];
            pa[0] = packh2(sacc[2*kc][0],   sacc[2*kc][1]);
            pa[1] = packh2(sacc[2*kc][2],   sacc[2*kc][3]);
            pa[2] = packh2(sacc[2*kc+1][0], sacc[2*kc+1][1]);
            pa[3] = packh2(sacc[2*kc+1][2], sacc[2*kc+1][3]);
            const uint32_t vrow = bv_base + (uint32_t)(kc * 16 * FLD * 2);
#pragma unroll
            for (int vg = 0; vg < 2; vg++) {
                const uint32_t bo = kvb + vrow + (uint32_t)(vg * 32 * 2);
                uint32_t tvr[4], tvi[4];
                LDSM4T(tvr, bo + 2*FQT_B);
                LDSM4T(tvi, bo + 3*FQT_B);
                uint32_t blo[2] = {tvr[0], tvr[1]}, bhi[2] = {tvr[2], tvr[3]};
                MMA_F16(oR[4*vg],   pa, blo);
                MMA_F16(oR[4*vg+1], pa, bhi);
                blo[0] = tvi[0]; blo[1] = tvi[1]; bhi[0] = tvi[2]; bhi[1] = tvi[3];
                MMA_F16(oI[4*vg],   pa, blo);
                MMA_F16(oI[4*vg+1], pa, bhi);
            }
#pragma unroll
            for (int vg = 0; vg < 2; vg++) {
                const uint32_t bo = kvb + vrow + (uint32_t)((vg * 32 + 16) * 2);
                uint32_t tvr[4], tvi[4];
                LDSM4T(tvr, bo + 2*FQT_B);
                LDSM4T(tvi, bo + 3*FQT_B);
                uint32_t blo[2] = {tvr[0], tvr[1]}, bhi[2] = {tvr[2], tvr[3]};
                MMA_F16(oR[4*vg+2], pa, blo);
                MMA_F16(oR[4*vg+3], pa, bhi);
                blo[0] = tvi[0]; blo[1] = tvi[1]; bhi[0] = tvi[2]; bhi[1] = tvi[3];
                MMA_F16(oI[4*vg+2], pa, blo);
                MMA_F16(oI[4*vg+3], pa, bhi);
            }
        }
        if (kt < tile) CP_WAIT0();
        __syncthreads();
    }

    // ---- epilogue: O / s -> half ------------------------------------------
    const float inv0 = 1.f / s0, inv1 = 1.f / s1;
#pragma unroll
    for (int nt = 0; nt < 8; nt++) {
        const int col = nt*8 + 2*t4;
        const size_t p0 = off + (size_t)row0 * Dn + col;
        const size_t p1 = off + (size_t)row1 * Dn + col;
        *(__half2*)(Or + p0) = __floats2half2_rn(oR[nt][0]*inv0, oR[nt][1]*inv0);
        *(__half2*)(Oi + p0) = __floats2half2_rn(oI[nt][0]*inv0, oI[nt][1]*inv0);
        *(__half2*)(Or + p1) = __floats2half2_rn(oR[nt][2]*inv1, oR[nt][3]*inv1);
        *(__half2*)(Oi + p1) = __floats2half2_rn(oI[nt][2]*inv1, oI[nt][3]*inv1);
    }
}

// ---------------- complex layernorm (fp32 in, half out) ---------------------
__global__ void cln16(const float* __restrict__ xr, const float* __restrict__ xi,
                      const float* __restrict__ gr, const float* __restrict__ gi,
                      const float* __restrict__ bre, const float* __restrict__ bim,
                      __half* __restrict__ outr, __half* __restrict__ outi)
{
    int row = blockIdx.x;
    const float* pr = xr + (size_t)row * Dn;
    const float* pi = xi + (size_t)row * Dn;
    __shared__ float s1[256], s2[256];
    int tid = threadIdx.x;
    float sr = 0.f, si = 0.f;
    for (int j = tid; j < Dn; j += 256) { sr += pr[j]; si += pi[j]; }
    s1[tid] = sr; s2[tid] = si;
    __syncthreads();
    for (int o = 128; o > 0; o >>= 1) {
        if (tid < o) { s1[tid] += s1[tid+o]; s2[tid] += s2[tid+o]; }
        __syncthreads();
    }
    float mr = s1[0] * (1.f/Dn), mi = s2[0] * (1.f/Dn);
    __syncthreads();
    float v = 0.f;
    for (int j = tid; j < Dn; j += 256) {
        float cr = pr[j] - mr, ci = pi[j] - mi;
        v += cr*cr + ci*ci;
    }
    s1[tid] = v;
    __syncthreads();
    for (int o = 128; o > 0; o >>= 1) {
        if (tid < o) s1[tid] += s1[tid+o];
        __syncthreads();
    }
    float inv = rsqrtf(s1[0] * (1.f/Dn) + EPSc);
    for (int j = tid; j < Dn; j += 256) {
        float nr = (pr[j]-mr)*inv, ni = (pi[j]-mi)*inv;
        outr[(size_t)row*Dn + j] = __float2half_rn(nr*gr[j] - ni*gi[j] + bre[j]);
        outi[(size_t)row*Dn + j] = __float2half_rn(nr*gi[j] + ni*gr[j] + bim[j]);
    }
}

// ---------------- RoPE (in place on half arrays) ----------------------------
__global__ void rope16(__half* __restrict__ xr, __half* __restrict__ xi)
{
    int idx = blockIdx.x * blockDim.x + threadIdx.x;
    int j = idx & 31;
    int t = idx >> 5;
    int h = t & (Hn-1); t >>= 4;
    int l = t & (Ln-1);
    int b = t >> 10;
    size_t base = ((size_t)(b*Ln + l)) * Dn + h * HDn;
    double invf = exp(-((double)(2*j) / (double)HDn) * 9.210340371976184);
    double th = (double)l * invf;
    double sd, cd;
    sincos(th, &sd, &cd);
    float c = (float)cd, s = (float)sd;
    float a0 = __half2float(xr[base+j]), a1 = __half2float(xr[base+j+32]);
    xr[base+j]    = __float2half_rn(a0*c - a1*s);
    xr[base+j+32] = __float2half_rn(a1*c + a0*s);
    float b0 = __half2float(xi[base+j]), b1 = __half2float(xi[base+j+32]);
    xi[base+j]    = __float2half_rn(b0*c - b1*s);
    xi[base+j+32] = __float2half_rn(b1*c + b0*s);
}

// ---------------- ModReLU (fp32 in, half out) -------------------------------
__global__ void modrelu16(const float* __restrict__ fr, const float* __restrict__ fi,
                          __half* __restrict__ gr, __half* __restrict__ gi,
                          const float* __restrict__ mb)
{
    size_t idx = (size_t)blockIdx.x * blockDim.x + threadIdx.x;
    int col = (int)(idx & (HIDn - 1));
    float r = fr[idx], i = fi[idx];
    float mag = sqrtf(r*r + i*i);
    float safe = mag > 0.f ? mag : 1.f;
    float act = fmaxf(mag + mb[col], 0.f);
    float fac = act / safe;
    gr[idx] = __float2half_rn(r * fac);
    gi[idx] = __float2half_rn(i * fac);
}

// ---------------- launch ----------------------------------------------------
extern "C" void kernel_launch(void* const* d_in, const int* in_sizes, int n_in,
                              void* d_out, int out_size)
{
    const float* x_r   = (const float*)d_in[0];
    const float* x_i   = (const float*)d_in[1];
    const float* Wq_r  = (const float*)d_in[2];
    const float* Wq_i  = (const float*)d_in[3];
    const float* Wk_r  = (const float*)d_in[4];
    const float* Wk_i  = (const float*)d_in[5];
    const float* Wv_r  = (const float*)d_in[6];
    const float* Wv_i  = (const float*)d_in[7];
    const float* Wo_r  = (const float*)d_in[8];
    const float* Wo_i  = (const float*)d_in[9];
    const float* bo_r  = (const float*)d_in[10];
    const float* bo_i  = (const float*)d_in[11];
    const float* ln1_gr = (const float*)d_in[12];
    const float* ln1_gi = (const float*)d_in[13];
    const float* ln1_br = (const float*)d_in[14];
    const float* ln1_bi = (const float*)d_in[15];
    const float* ln2_gr = (const float*)d_in[16];
    const float* ln2_gi = (const float*)d_in[17];
    const float* ln2_br = (const float*)d_in[18];
    const float* ln2_bi = (const float*)d_in[19];
    const float* W1_r  = (const float*)d_in[20];
    const float* W1_i  = (const float*)d_in[21];
    const float* b1_r  = (const float*)d_in[22];
    const float* b1_i  = (const float*)d_in[23];
    const float* W2_r  = (const float*)d_in[24];
    const float* W2_i  = (const float*)d_in[25];
    const float* b2_r  = (const float*)d_in[26];
    const float* b2_i  = (const float*)d_in[27];
    const float* mod_b = (const float*)d_in[28];
    float* out = (float*)d_out;

    __half *h16r, *h16i, *q16r, *q16i, *k16r, *k16i, *v16r, *v16i;
    __half *ao16r, *ao16i, *f16r, *f16i;
    __half *wq16r, *wq16i, *wk16r, *wk16i, *wv16r, *wv16i, *wo16r, *wo16i;
    __half *w116r, *w116i, *w216r, *w216i;
    float *ar, *ai, *fr, *fi;
    cudaGetSymbolAddress((void**)&h16r, g_h16r);  cudaGetSymbolAddress((void**)&h16i, g_h16i);
    cudaGetSymbolAddress((void**)&q16r, g_q16r);  cudaGetSymbolAddress((void**)&q16i, g_q16i);
    cudaGetSymbolAddress((void**)&k16r, g_k16r);  cudaGetSymbolAddress((void**)&k16i, g_k16i);
    cudaGetSymbolAddress((void**)&v16r, g_v16r);  cudaGetSymbolAddress((void**)&v16i, g_v16i);
    cudaGetSymbolAddress((void**)&ao16r, g_ao16r);cudaGetSymbolAddress((void**)&ao16i, g_ao16i);
    cudaGetSymbolAddress((void**)&ar, g_ar);      cudaGetSymbolAddress((void**)&ai, g_ai);
    cudaGetSymbolAddress((void**)&fr, g_fr);      cudaGetSymbolAddress((void**)&fi, g_fi);
    cudaGetSymbolAddress((void**)&f16r, g_f16r);  cudaGetSymbolAddress((void**)&f16i, g_f16i);
    cudaGetSymbolAddress((void**)&wq16r, g_wq16r);cudaGetSymbolAddress((void**)&wq16i, g_wq16i);
    cudaGetSymbolAddress((void**)&wk16r, g_wk16r);cudaGetSymbolAddress((void**)&wk16i, g_wk16i);
    cudaGetSymbolAddress((void**)&wv16r, g_wv16r);cudaGetSymbolAddress((void**)&wv16i, g_wv16i);
    cudaGetSymbolAddress((void**)&wo16r, g_wo16r);cudaGetSymbolAddress((void**)&wo16i, g_wo16i);
    cudaGetSymbolAddress((void**)&w116r, g_w116r);cudaGetSymbolAddress((void**)&w116i, g_w116i);
    cudaGetSymbolAddress((void**)&w216r, g_w216r);cudaGetSymbolAddress((void**)&w216i, g_w216i);

    cudaFuncSetAttribute(hgemm,   cudaFuncAttributeMaxDynamicSharedMemorySize, SMEM_GEMM);
    cudaFuncSetAttribute(flash16, cudaFuncAttributeMaxDynamicSharedMemorySize, SMEM_FA);

    // 0. weight conversion to fp16
    const int n4d = Dn*Dn/4, n4h = HIDn*Dn/4;
    wprep16<<<n4d/256, 256>>>((const float4*)Wq_r, (const float4*)Wq_i, (__half2*)wq16r, (__half2*)wq16i, n4d);
    wprep16<<<n4d/256, 256>>>((const float4*)Wk_r, (const float4*)Wk_i, (__half2*)wk16r, (__half2*)wk16i, n4d);
    wprep16<<<n4d/256, 256>>>((const float4*)Wv_r, (const float4*)Wv_i, (__half2*)wv16r, (__half2*)wv16i, n4d);
    wprep16<<<n4d/256, 256>>>((const float4*)Wo_r, (const float4*)Wo_i, (__half2*)wo16r, (__half2*)wo16i, n4d);
    wprep16<<<n4h/256, 256>>>((const float4*)W1_r, (const float4*)W1_i, (__half2*)w116r, (__half2*)w116i, n4h);
    wprep16<<<n4h/256, 256>>>((const float4*)W2_r, (const float4*)W2_i, (__half2*)w216r, (__half2*)w216i, n4h);

    // 1. LN1 -> half
    cln16<<<Mn, 256>>>(x_r, x_i, ln1_gr, ln1_gi, ln1_br, ln1_bi, h16r, h16i);

    // 2. QKV projections (half in, half out)
    dim3 gproj(Dn/BNg, Mn/BMg);
    hgemm<<<gproj, 256, SMEM_GEMM>>>(h16r, h16i, wq16r, wq16i, nullptr, nullptr, q16r, q16i, Mn, Dn, Dn, nullptr, nullptr, nullptr, nullptr);
    hgemm<<<gproj, 256, SMEM_GEMM>>>(h16r, h16i, wk16r, wk16i, nullptr, nullptr, k16r, k16i, Mn, Dn, Dn, nullptr, nullptr, nullptr, nullptr);
    hgemm<<<gproj, 256, SMEM_GEMM>>>(h16r, h16i, wv16r, wv16i, nullptr, nullptr, v16r, v16i, Mn, Dn, Dn, nullptr, nullptr, nullptr, nullptr);

    // 3. RoPE on Q and K (half in place)
    rope16<<<(Bn*Ln*Hn*32)/256, 256>>>(q16r, q16i);
    rope16<<<(Bn*Ln*Hn*32)/256, 256>>>(k16r, k16i);

    // 4. fused flash attention -> ao16
    flash16<<<dim3(Ln/128, Bn*Hn), 256, SMEM_FA>>>(q16r, q16i, k16r, k16i, v16r, v16i, ao16r, ao16i);

    // 5. out projection + bias + residual(x) -> fp32
    hgemm<<<gproj, 256, SMEM_GEMM>>>(ao16r, ao16i, wo16r, wo16i, ar, ai, nullptr, nullptr, Mn, Dn, Dn, bo_r, bo_i, x_r, x_i);

    // 6. LN2 -> half
    cln16<<<Mn, 256>>>(ar, ai, ln2_gr, ln2_gi, ln2_br, ln2_bi, h16r, h16i);

    // 7. FC1 + bias -> fp32
    hgemm<<<dim3(HIDn/BNg, Mn/BMg), 256, SMEM_GEMM>>>(h16r, h16i, w116r, w116i, fr, fi, nullptr, nullptr, Mn, HIDn, Dn, b1_r, b1_i, nullptr, nullptr);

    // 8. ModReLU -> half
    modrelu16<<<(Mn*(size_t)HIDn)/256, 256>>>(fr, fi, f16r, f16i, mod_b);

    // 9. FC2 + bias + residual(ar/ai) -> output (fp32)
    hgemm<<<gproj, 256, SMEM_GEMM>>>(f16r, f16i, w216r, w216i, out, out + (size_t)Mn*Dn, nullptr, nullptr, Mn, Dn, HIDn, b2_r, b2_i, ar, ai);
}